// round 2
// baseline (speedup 1.0000x reference)
#include <cuda_runtime.h>
#include <math.h>

// Problem constants
#define BATCH 16384
#define QDIM  1024
#define N1    4096   // 4*Q
#define N2    2048   // 2*Q

// ---------------------------------------------------------------------------
// Scratch (device globals — allocation-free rule)
// ---------------------------------------------------------------------------
__device__ float g_stats[2][9];                       // weight moments (amp, ph)
__device__ float g_h1[(size_t)BATCH * N1];            // 256 MB
__device__ float g_h2[(size_t)BATCH * N2];            // 128 MB
__device__ float g_p [(size_t)BATCH * N2];            // 128 MB
__device__ float g_amp[(size_t)BATCH * QDIM];         // 64 MB
__device__ float g_phs[(size_t)BATCH * QDIM];         // 64 MB
__device__ float g_qs[(size_t)BATCH * QDIM];          // 64 MB
__device__ float g_v [(size_t)BATCH * QDIM];          // 64 MB

// ---------------------------------------------------------------------------
// Moments: LN of (x @ W1^T + b) with F=2 has closed-form row stats:
//   y_j = x0*w0_j + x1*w1_j + b_j
//   mean   = x0*E[w0] + x1*E[w1] + E[b]
//   E[y^2] = x0^2 E[w0^2] + x1^2 E[w1^2] + E[b^2]
//          + 2(x0 x1 E[w0 w1] + x0 E[w0 b] + x1 E[w1 b])
// Precompute the 9 moments once (double accumulate).
// ---------------------------------------------------------------------------
__global__ void moments_kernel(const float* __restrict__ W,
                               const float* __restrict__ bv,
                               int N, int which) {
    int tid = threadIdx.x;
    double acc[9];
#pragma unroll
    for (int q = 0; q < 9; q++) acc[q] = 0.0;
    for (int j = tid; j < N; j += 256) {
        double w0 = W[2 * j], w1 = W[2 * j + 1], b = bv[j];
        acc[0] += w0;      acc[1] += w1;      acc[2] += b;
        acc[3] += w0 * w0; acc[4] += w1 * w1; acc[5] += b * b;
        acc[6] += w0 * w1; acc[7] += w0 * b;  acc[8] += w1 * b;
    }
    __shared__ double sd[256];
    for (int q = 0; q < 9; q++) {
        sd[tid] = acc[q];
        __syncthreads();
        for (int s = 128; s > 0; s >>= 1) {
            if (tid < s) sd[tid] += sd[tid + s];
            __syncthreads();
        }
        if (tid == 0) g_stats[which][q] = (float)(sd[0] / N);
        __syncthreads();
    }
}

// ---------------------------------------------------------------------------
// Layer-1 (both branches): fully elementwise thanks to closed-form LN stats.
// act: 0 = exact gelu, 1 = silu
// ---------------------------------------------------------------------------
__global__ void layer1_kernel(const float* __restrict__ x,
                              const float* __restrict__ W,
                              const float* __restrict__ bv,
                              const float* __restrict__ gam,
                              const float* __restrict__ bet,
                              float* __restrict__ out,
                              int N, int which, int act) {
    int nv = N >> 2;                       // float4 groups per row
    int i = blockIdx.x * blockDim.x + threadIdx.x;
    int total = BATCH * nv;
    if (i >= total) return;
    int b = i / nv;
    int j = (i - b * nv) << 2;

    float x0 = __ldg(x + 2 * b), x1 = __ldg(x + 2 * b + 1);
    const float* s = g_stats[which];
    float m  = x0 * s[0] + x1 * s[1] + s[2];
    float E2 = x0 * x0 * s[3] + x1 * x1 * s[4] + s[5]
             + 2.f * (x0 * x1 * s[6] + x0 * s[7] + x1 * s[8]);
    float var = E2 - m * m;
    float rstd = rsqrtf(fmaxf(var, 0.f) + 1e-5f);

    float4 wA = *(const float4*)(W + 2 * j);       // w0[j],w1[j],w0[j+1],w1[j+1]
    float4 wB = *(const float4*)(W + 2 * j + 4);
    float4 bb = *(const float4*)(bv + j);
    float4 gg = *(const float4*)(gam + j);
    float4 ee = *(const float4*)(bet + j);

    float y[4];
    y[0] = x0 * wA.x + x1 * wA.y + bb.x;
    y[1] = x0 * wA.z + x1 * wA.w + bb.y;
    y[2] = x0 * wB.x + x1 * wB.y + bb.z;
    y[3] = x0 * wB.z + x1 * wB.w + bb.w;

    float gv[4] = {gg.x, gg.y, gg.z, gg.w};
    float ev[4] = {ee.x, ee.y, ee.z, ee.w};
    float o[4];
#pragma unroll
    for (int q = 0; q < 4; q++) {
        float t = (y[q] - m) * rstd * gv[q] + ev[q];
        if (act == 0) {
            o[q] = 0.5f * t * (1.0f + erff(t * 0.70710678118654752f));
        } else {
            o[q] = t / (1.0f + expf(-t));
        }
    }
    *(float4*)(out + (size_t)b * N + j) = make_float4(o[0], o[1], o[2], o[3]);
}

// ---------------------------------------------------------------------------
// SGEMM (NT): C[M,N] = A[M,K] @ W[N,K]^T + bias[N]; ACT: 0=none, 1=tanh
// 128x128 tile, BK=16, 256 threads, 8x8 per-thread micro-tile.
// All M,N divisible by 128 and K by 16 for this problem — no bounds checks.
// ---------------------------------------------------------------------------
template <int ACT>
__global__ __launch_bounds__(256, 2)
void sgemm_nt(const float* __restrict__ A, const float* __restrict__ W,
              const float* __restrict__ bias, float* __restrict__ C,
              int N, int K) {
    __shared__ float As[16][128];
    __shared__ float Bs[16][128];

    int tid = threadIdx.x;
    int bn = blockIdx.x * 128;
    int bm = blockIdx.y * 128;
    int tx = tid & 15;          // 0..15 -> n
    int ty = tid >> 4;          // 0..15 -> m

    const float* Aptr = A + (size_t)bm * K;
    const float* Wptr = W + (size_t)bn * K;

    int lrow = tid >> 2;        // 0..63
    int lcol = (tid & 3) << 2;  // 0,4,8,12

    float acc[8][8];
#pragma unroll
    for (int i = 0; i < 8; i++)
#pragma unroll
        for (int j = 0; j < 8; j++) acc[i][j] = 0.f;

    for (int k0 = 0; k0 < K; k0 += 16) {
#pragma unroll
        for (int h = 0; h < 2; h++) {
            int r = lrow + h * 64;
            float4 va = *(const float4*)(Aptr + (size_t)r * K + k0 + lcol);
            As[lcol + 0][r] = va.x;
            As[lcol + 1][r] = va.y;
            As[lcol + 2][r] = va.z;
            As[lcol + 3][r] = va.w;
            float4 vb = *(const float4*)(Wptr + (size_t)r * K + k0 + lcol);
            Bs[lcol + 0][r] = vb.x;
            Bs[lcol + 1][r] = vb.y;
            Bs[lcol + 2][r] = vb.z;
            Bs[lcol + 3][r] = vb.w;
        }
        __syncthreads();
#pragma unroll
        for (int kk = 0; kk < 16; kk++) {
            float a[8], bfr[8];
#pragma unroll
            for (int i = 0; i < 8; i++) a[i] = As[kk][ty * 8 + i];
#pragma unroll
            for (int j = 0; j < 8; j++) bfr[j] = Bs[kk][tx * 8 + j];
#pragma unroll
            for (int i = 0; i < 8; i++)
#pragma unroll
                for (int j = 0; j < 8; j++) acc[i][j] += a[i] * bfr[j];
        }
        __syncthreads();
    }

    int n0 = bn + tx * 8;
    float4 bs0 = *(const float4*)(bias + n0);
    float4 bs1 = *(const float4*)(bias + n0 + 4);
    float bvv[8] = {bs0.x, bs0.y, bs0.z, bs0.w, bs1.x, bs1.y, bs1.z, bs1.w};
#pragma unroll
    for (int i = 0; i < 8; i++) {
        int m = bm + ty * 8 + i;
        float r[8];
#pragma unroll
        for (int j = 0; j < 8; j++) {
            float c = acc[i][j] + bvv[j];
            if (ACT == 1) c = tanhf(c);
            r[j] = c;
        }
        *(float4*)(C + (size_t)m * N + n0)     = make_float4(r[0], r[1], r[2], r[3]);
        *(float4*)(C + (size_t)m * N + n0 + 4) = make_float4(r[4], r[5], r[6], r[7]);
    }
}

// ---------------------------------------------------------------------------
// Per-row LayerNorm(+tanh) over N=2048, in-place. One block (256 thr) per row.
// ---------------------------------------------------------------------------
__global__ void ln_tanh_rows(float* __restrict__ data,
                             const float* __restrict__ gam,
                             const float* __restrict__ bet) {
    const int N = 2048;
    int row = blockIdx.x, tid = threadIdx.x;
    float* p = data + (size_t)row * N;

    float v[8];
    float s = 0.f, s2 = 0.f;
#pragma unroll
    for (int i = 0; i < 8; i++) {
        float t = p[tid + i * 256];
        v[i] = t;
        s += t;
        s2 += t * t;
    }
#pragma unroll
    for (int o = 16; o > 0; o >>= 1) {
        s  += __shfl_down_sync(0xffffffffu, s, o);
        s2 += __shfl_down_sync(0xffffffffu, s2, o);
    }
    __shared__ float sh[2][8];
    __shared__ float mb[2];
    int w = tid >> 5, l = tid & 31;
    if (l == 0) { sh[0][w] = s; sh[1][w] = s2; }
    __syncthreads();
    if (tid == 0) {
        float S = 0.f, S2 = 0.f;
#pragma unroll
        for (int q = 0; q < 8; q++) { S += sh[0][q]; S2 += sh[1][q]; }
        float mean = S / N;
        float var = S2 / N - mean * mean;
        mb[0] = mean;
        mb[1] = rsqrtf(fmaxf(var, 0.f) + 1e-5f);
    }
    __syncthreads();
    float mean = mb[0], rstd = mb[1];
#pragma unroll
    for (int i = 0; i < 8; i++) {
        int c = tid + i * 256;
        float t = (v[i] - mean) * rstd * gam[c] + bet[c];
        p[c] = tanhf(t);
    }
}

// ---------------------------------------------------------------------------
// qs = (sin(amp*f0+p0) + cos(phase*f1+p1) + tanh(p2)) / 3, using rot[D-1=4]
// ---------------------------------------------------------------------------
__global__ void qs_kernel(const float* __restrict__ amp,
                          const float* __restrict__ phase,
                          const float* __restrict__ rot_freq,
                          const float* __restrict__ rot_phase,
                          float* __restrict__ qs) {
    int i = blockIdx.x * blockDim.x + threadIdx.x;   // over BATCH*QDIM/4
    if (i >= BATCH * (QDIM / 4)) return;
    int jv = i & (QDIM / 4 - 1);
    int j = jv << 2;
    float4 a  = *(const float4*)(amp + (size_t)i * 4);
    float4 ph = *(const float4*)(phase + (size_t)i * 4);
    const float* rf = rot_freq  + (size_t)(4 * QDIM + j) * 3;
    const float* rp = rot_phase + (size_t)(4 * QDIM + j) * 3;
    float av[4] = {a.x, a.y, a.z, a.w};
    float pv[4] = {ph.x, ph.y, ph.z, ph.w};
    float o[4];
#pragma unroll
    for (int q = 0; q < 4; q++) {
        float rx = sinf(av[q] * rf[3 * q + 0] + rp[3 * q + 0]);
        float ry = cosf(pv[q] * rf[3 * q + 1] + rp[3 * q + 1]);
        float rz = tanhf(rp[3 * q + 2]);
        o[q] = (rx + ry + rz) * (1.0f / 3.0f);
    }
    *(float4*)(qs + (size_t)i * 4) = make_float4(o[0], o[1], o[2], o[3]);
}

// ---------------------------------------------------------------------------
// Launch
// ---------------------------------------------------------------------------
extern "C" void kernel_launch(void* const* d_in, const int* in_sizes, int n_in,
                              void* d_out, int out_size) {
    const float* x         = (const float*)d_in[0];
    const float* amp_W1    = (const float*)d_in[1];
    const float* amp_b1    = (const float*)d_in[2];
    const float* amp_g1    = (const float*)d_in[3];
    const float* amp_be1   = (const float*)d_in[4];
    const float* amp_W2    = (const float*)d_in[5];
    const float* amp_b2    = (const float*)d_in[6];
    const float* amp_g2    = (const float*)d_in[7];
    const float* amp_be2   = (const float*)d_in[8];
    const float* amp_W3    = (const float*)d_in[9];
    const float* amp_b3    = (const float*)d_in[10];
    const float* ph_W1     = (const float*)d_in[11];
    const float* ph_b1     = (const float*)d_in[12];
    const float* ph_g1     = (const float*)d_in[13];
    const float* ph_be1    = (const float*)d_in[14];
    const float* ph_W2     = (const float*)d_in[15];
    const float* ph_b2     = (const float*)d_in[16];
    const float* rot_freq  = (const float*)d_in[17];
    const float* rot_phase = (const float*)d_in[18];
    const float* attn_in_w = (const float*)d_in[19];
    const float* attn_in_b = (const float*)d_in[20];
    const float* attn_out_w= (const float*)d_in[21];
    const float* attn_out_b= (const float*)d_in[22];
    float* out = (float*)d_out;

    float *h1, *h2, *p, *amp, *phs, *qs, *v;
    cudaGetSymbolAddress((void**)&h1,  g_h1);
    cudaGetSymbolAddress((void**)&h2,  g_h2);
    cudaGetSymbolAddress((void**)&p,   g_p);
    cudaGetSymbolAddress((void**)&amp, g_amp);
    cudaGetSymbolAddress((void**)&phs, g_phs);
    cudaGetSymbolAddress((void**)&qs,  g_qs);
    cudaGetSymbolAddress((void**)&v,   g_v);

    // 1. closed-form LN stats for the two F=2 layers
    moments_kernel<<<1, 256>>>(amp_W1, amp_b1, N1, 0);
    moments_kernel<<<1, 256>>>(ph_W1,  ph_b1,  N2, 1);

    // 2. layer-1 (elementwise)
    {
        int blocks = (BATCH * (N1 / 4) + 255) / 256;
        layer1_kernel<<<blocks, 256>>>(x, amp_W1, amp_b1, amp_g1, amp_be1,
                                       h1, N1, 0, /*gelu*/0);
    }
    {
        int blocks = (BATCH * (N2 / 4) + 255) / 256;
        layer1_kernel<<<blocks, 256>>>(x, ph_W1, ph_b1, ph_g1, ph_be1,
                                       p, N2, 1, /*silu*/1);
    }

    // 3. amp branch: h2 = tanh(LN(h1 @ W2^T + b2))
    sgemm_nt<0><<<dim3(N2 / 128, BATCH / 128), 256>>>(h1, amp_W2, amp_b2, h2, N2, N1);
    ln_tanh_rows<<<BATCH, 256>>>(h2, amp_g2, amp_be2);

    // 4. amp = h2 @ W3^T + b3
    sgemm_nt<0><<<dim3(QDIM / 128, BATCH / 128), 256>>>(h2, amp_W3, amp_b3, amp, QDIM, N2);

    // 5. phase = tanh(p @ ph_W2^T + b2)
    sgemm_nt<1><<<dim3(QDIM / 128, BATCH / 128), 256>>>(p, ph_W2, ph_b2, phs, QDIM, N2);

    // 6. qs mix
    {
        int blocks = (BATCH * (QDIM / 4) + 255) / 256;
        qs_kernel<<<blocks, 256>>>(amp, phs, rot_freq, rot_phase, qs);
    }

    // 7. v = qs @ attn_in_w[2Q:]^T + attn_in_b[2Q:]   (only V slice of qkv used)
    sgemm_nt<0><<<dim3(QDIM / 128, BATCH / 128), 256>>>(
        qs, attn_in_w + (size_t)2 * QDIM * QDIM, attn_in_b + 2 * QDIM, v, QDIM, QDIM);

    // 8. out = v @ attn_out_w^T + attn_out_b
    sgemm_nt<0><<<dim3(QDIM / 128, BATCH / 128), 256>>>(v, attn_out_w, attn_out_b, out, QDIM, QDIM);
}

// round 5
// speedup vs baseline: 2.4423x; 2.4423x over previous
#include <cuda_runtime.h>
#include <cuda_bf16.h>
#include <math.h>
#include <stdint.h>

#define BATCH 16384
#define QDIM  1024
#define N1    4096
#define N2    2048

typedef __nv_bfloat16 bf16;

// ---------------------------------------------------------------------------
// Scratch (device globals — allocation-free rule)
// ---------------------------------------------------------------------------
__device__ float g_stats[2][9];
__device__ bf16  g_h1h[(size_t)BATCH * N1];
__device__ bf16  g_h1l[(size_t)BATCH * N1];
__device__ float g_h2 [(size_t)BATCH * N2];
__device__ bf16  g_h2th[(size_t)BATCH * N2];
__device__ bf16  g_h2tl[(size_t)BATCH * N2];
__device__ bf16  g_ph [(size_t)BATCH * N2];
__device__ bf16  g_pl [(size_t)BATCH * N2];
__device__ float g_amp[(size_t)BATCH * QDIM];
__device__ float g_phs[(size_t)BATCH * QDIM];
__device__ bf16  g_qsh[(size_t)BATCH * QDIM];
__device__ bf16  g_qsl[(size_t)BATCH * QDIM];
__device__ bf16  g_vh [(size_t)BATCH * QDIM];
__device__ bf16  g_vl [(size_t)BATCH * QDIM];
__device__ bf16  g_w2h[(size_t)N2 * N1],  g_w2l[(size_t)N2 * N1];
__device__ bf16  g_w3h[(size_t)QDIM * N2], g_w3l[(size_t)QDIM * N2];
__device__ bf16  g_pw2h[(size_t)QDIM * N2], g_pw2l[(size_t)QDIM * N2];
__device__ bf16  g_wvh[(size_t)QDIM * QDIM], g_wvl[(size_t)QDIM * QDIM];
__device__ bf16  g_woh[(size_t)QDIM * QDIM], g_wol[(size_t)QDIM * QDIM];

// ---------------------------------------------------------------------------
// Helpers
// ---------------------------------------------------------------------------
__device__ __forceinline__ uint32_t smem_u32(const void* p) {
    uint32_t a;
    asm("{ .reg .u64 t; cvta.to.shared.u64 t, %1; cvt.u32.u64 %0, t; }"
        : "=r"(a) : "l"(p));
    return a;
}
__device__ __forceinline__ size_t gaddr(const void* p) {
    size_t r;
    asm("cvta.to.global.u64 %0, %1;" : "=l"(r) : "l"(p));
    return r;
}
static __device__ __forceinline__ uint32_t swz128(uint32_t x) {
    return x ^ ((x >> 3) & 0x70);
}

// ---------------------------------------------------------------------------
// Split-precision bf16 GEMM via mma.sync (HMMA, arch-generic):
//   C[M,N] = (Ah+Al)[M,K] @ (Bh+Bl)[N,K]^T + bias
// expressed as K-concatenation: [Ah|Al|Ah] @ [Bh|Bh|Bl]^T (Al*Bl dropped).
// CTA 128x128, BK=64, 8 warps (64x32 warp tiles), cp.async double buffer.
// EPI: 0 = fp32 out, 1 = tanh fp32 out, 2 = bf16 hi/lo split out.
// ---------------------------------------------------------------------------
#define BM 128
#define BN 128
#define BK 64
#define A_BYTES (BM * BK * 2)          // 16384
#define B_BYTES (BN * BK * 2)          // 16384
#define STAGE_BYTES (A_BYTES + B_BYTES)
#define SMEM_MMA (2 * STAGE_BYTES)     // 65536

template <int EPI>
__global__ __launch_bounds__(256)
void gemm_mma(const bf16* __restrict__ Ah, const bf16* __restrict__ Al,
              const bf16* __restrict__ Bh, const bf16* __restrict__ Bl,
              const float* __restrict__ bias,
              float* __restrict__ Cf, bf16* __restrict__ Chi, bf16* __restrict__ Clo,
              int Ntot, int K) {
    extern __shared__ char smem[];
    uint32_t sbase = smem_u32(smem);
    int tid = threadIdx.x, lane = tid & 31, wid = tid >> 5;
    int bm = blockIdx.y * BM, bn = blockIdx.x * BN;
    int wm = (wid >> 2) * 64, wn = (wid & 3) * 32;

    const int kc_per = K / BK;
    const int nIt = 3 * kc_per;

    float acc[16][4];
#pragma unroll
    for (int i = 0; i < 16; i++)
#pragma unroll
        for (int j = 0; j < 4; j++) acc[i][j] = 0.f;

    // precomputed per-thread load indices
    int lrow = tid >> 3;        // 0..31 (base row; +32*i)
    int lcol = (tid & 7) * 16;  // byte column within 128B row

    auto issue_stage = [&](int it, int stage) {
        int phase = it / kc_per;
        int kc = it - phase * kc_per;
        const bf16* As = (phase == 1) ? Al : Ah;
        const bf16* Bs = (phase == 2) ? Bl : Bh;
        uint32_t sA = sbase + stage * STAGE_BYTES;
        uint32_t sB = sA + A_BYTES;
        int kb = kc * BK + (tid & 7) * 8;   // element offset in K
#pragma unroll
        for (int i = 0; i < 4; i++) {
            int row = lrow + i * 32;
            size_t g = gaddr(As + (size_t)(bm + row) * K + kb);
            uint32_t s = sA + swz128((uint32_t)(row * 128 + lcol));
            asm volatile("cp.async.cg.shared.global [%0], [%1], 16;" :: "r"(s), "l"(g));
        }
#pragma unroll
        for (int i = 0; i < 4; i++) {
            int row = lrow + i * 32;
            size_t g = gaddr(Bs + (size_t)(bn + row) * K + kb);
            uint32_t s = sB + swz128((uint32_t)(row * 128 + lcol));
            asm volatile("cp.async.cg.shared.global [%0], [%1], 16;" :: "r"(s), "l"(g));
        }
        asm volatile("cp.async.commit_group;" ::: "memory");
    };

    issue_stage(0, 0);

    for (int it = 0; it < nIt; it++) {
        int cur = it & 1, nxt = cur ^ 1;
        if (it + 1 < nIt) {
            issue_stage(it + 1, nxt);
            asm volatile("cp.async.wait_group 1;" ::: "memory");
        } else {
            asm volatile("cp.async.wait_group 0;" ::: "memory");
        }
        __syncthreads();

        uint32_t sA = sbase + cur * STAGE_BYTES;
        uint32_t sB = sA + A_BYTES;
#pragma unroll
        for (int ks = 0; ks < 4; ks++) {
            uint32_t a[4][4], b[4][2];
#pragma unroll
            for (int mi = 0; mi < 4; mi++) {
                int row = wm + mi * 16 + (lane & 15);
                uint32_t addr = sA + swz128((uint32_t)(row * 128 + ks * 32 + (lane >> 4) * 16));
                asm volatile("ldmatrix.sync.aligned.m8n8.x4.shared.b16 {%0,%1,%2,%3}, [%4];"
                             : "=r"(a[mi][0]), "=r"(a[mi][1]), "=r"(a[mi][2]), "=r"(a[mi][3])
                             : "r"(addr));
            }
#pragma unroll
            for (int ni = 0; ni < 4; ni++) {
                int row = wn + ni * 8 + (lane & 7);
                uint32_t addr = sB + swz128((uint32_t)(row * 128 + ks * 32 + ((lane >> 3) & 1) * 16));
                asm volatile("ldmatrix.sync.aligned.m8n8.x2.shared.b16 {%0,%1}, [%2];"
                             : "=r"(b[ni][0]), "=r"(b[ni][1]) : "r"(addr));
            }
#pragma unroll
            for (int mi = 0; mi < 4; mi++)
#pragma unroll
                for (int ni = 0; ni < 4; ni++) {
                    float* c = acc[mi * 4 + ni];
                    asm volatile(
                        "mma.sync.aligned.m16n8k16.row.col.f32.bf16.bf16.f32 "
                        "{%0,%1,%2,%3}, {%4,%5,%6,%7}, {%8,%9}, {%0,%1,%2,%3};"
                        : "+f"(c[0]), "+f"(c[1]), "+f"(c[2]), "+f"(c[3])
                        : "r"(a[mi][0]), "r"(a[mi][1]), "r"(a[mi][2]), "r"(a[mi][3]),
                          "r"(b[ni][0]), "r"(b[ni][1]));
                }
        }
        __syncthreads();
    }

    // epilogue
    int mb = bm + wm, nb = bn + wn;
#pragma unroll
    for (int mi = 0; mi < 4; mi++)
#pragma unroll
        for (int ni = 0; ni < 4; ni++) {
            float* c = acc[mi * 4 + ni];
            int r0 = mb + mi * 16 + (lane >> 2);
            int c0 = nb + ni * 8 + (lane & 3) * 2;
            float b0 = __ldg(bias + c0), b1 = __ldg(bias + c0 + 1);
            float y0 = c[0] + b0, y1 = c[1] + b1;
            float y2 = c[2] + b0, y3 = c[3] + b1;
            if (EPI == 1) {
                y0 = tanhf(y0); y1 = tanhf(y1); y2 = tanhf(y2); y3 = tanhf(y3);
            }
            if (EPI == 2) {
                bf16 h0 = __float2bfloat16(y0), h1 = __float2bfloat16(y1);
                bf16 h2 = __float2bfloat16(y2), h3 = __float2bfloat16(y3);
                __nv_bfloat162 hh0; hh0.x = h0; hh0.y = h1;
                __nv_bfloat162 hh1; hh1.x = h2; hh1.y = h3;
                __nv_bfloat162 ll0;
                ll0.x = __float2bfloat16(y0 - __bfloat162float(h0));
                ll0.y = __float2bfloat16(y1 - __bfloat162float(h1));
                __nv_bfloat162 ll1;
                ll1.x = __float2bfloat16(y2 - __bfloat162float(h2));
                ll1.y = __float2bfloat16(y3 - __bfloat162float(h3));
                *(__nv_bfloat162*)(Chi + (size_t)r0 * Ntot + c0)       = hh0;
                *(__nv_bfloat162*)(Chi + (size_t)(r0 + 8) * Ntot + c0) = hh1;
                *(__nv_bfloat162*)(Clo + (size_t)r0 * Ntot + c0)       = ll0;
                *(__nv_bfloat162*)(Clo + (size_t)(r0 + 8) * Ntot + c0) = ll1;
            } else {
                *(float2*)(Cf + (size_t)r0 * Ntot + c0)       = make_float2(y0, y1);
                *(float2*)(Cf + (size_t)(r0 + 8) * Ntot + c0) = make_float2(y2, y3);
            }
        }
}

// ---------------------------------------------------------------------------
// Weight split: fp32 -> bf16 hi + bf16 lo
// ---------------------------------------------------------------------------
__global__ void split_fp32(const float* __restrict__ in, bf16* __restrict__ hi,
                           bf16* __restrict__ lo, int n4) {
    int i = blockIdx.x * blockDim.x + threadIdx.x;
    if (i >= n4) return;
    float4 v = *(const float4*)(in + 4 * i);
    float xv[4] = {v.x, v.y, v.z, v.w};
    bf16 h[4], l[4];
#pragma unroll
    for (int q = 0; q < 4; q++) {
        h[q] = __float2bfloat16(xv[q]);
        l[q] = __float2bfloat16(xv[q] - __bfloat162float(h[q]));
    }
    __nv_bfloat162 h01; h01.x = h[0]; h01.y = h[1];
    __nv_bfloat162 h23; h23.x = h[2]; h23.y = h[3];
    __nv_bfloat162 l01; l01.x = l[0]; l01.y = l[1];
    __nv_bfloat162 l23; l23.x = l[2]; l23.y = l[3];
    *(__nv_bfloat162*)(hi + 4 * i)     = h01;
    *(__nv_bfloat162*)(hi + 4 * i + 2) = h23;
    *(__nv_bfloat162*)(lo + 4 * i)     = l01;
    *(__nv_bfloat162*)(lo + 4 * i + 2) = l23;
}

// ---------------------------------------------------------------------------
// Moments for the F=2 closed-form LN
// ---------------------------------------------------------------------------
__global__ void moments_kernel(const float* __restrict__ W,
                               const float* __restrict__ bv, int N, int which) {
    int tid = threadIdx.x;
    double acc[9];
#pragma unroll
    for (int q = 0; q < 9; q++) acc[q] = 0.0;
    for (int j = tid; j < N; j += 256) {
        double w0 = W[2 * j], w1 = W[2 * j + 1], b = bv[j];
        acc[0] += w0;      acc[1] += w1;      acc[2] += b;
        acc[3] += w0 * w0; acc[4] += w1 * w1; acc[5] += b * b;
        acc[6] += w0 * w1; acc[7] += w0 * b;  acc[8] += w1 * b;
    }
    __shared__ double sd[256];
    for (int q = 0; q < 9; q++) {
        sd[tid] = acc[q];
        __syncthreads();
        for (int s = 128; s > 0; s >>= 1) {
            if (tid < s) sd[tid] += sd[tid + s];
            __syncthreads();
        }
        if (tid == 0) g_stats[which][q] = (float)(sd[0] / N);
        __syncthreads();
    }
}

// ---------------------------------------------------------------------------
// Layer-1 (elementwise, closed-form LN) -> bf16 hi/lo. act: 0=gelu, 1=silu
// ---------------------------------------------------------------------------
__global__ void layer1_kernel(const float* __restrict__ x, const float* __restrict__ W,
                              const float* __restrict__ bv, const float* __restrict__ gam,
                              const float* __restrict__ bet,
                              bf16* __restrict__ ohi, bf16* __restrict__ olo,
                              int N, int which, int act) {
    int nv = N >> 2;
    int i = blockIdx.x * blockDim.x + threadIdx.x;
    if (i >= BATCH * nv) return;
    int b = i / nv;
    int j = (i - b * nv) << 2;

    float x0 = __ldg(x + 2 * b), x1 = __ldg(x + 2 * b + 1);
    const float* s = g_stats[which];
    float m  = x0 * s[0] + x1 * s[1] + s[2];
    float E2 = x0 * x0 * s[3] + x1 * x1 * s[4] + s[5]
             + 2.f * (x0 * x1 * s[6] + x0 * s[7] + x1 * s[8]);
    float rstd = rsqrtf(fmaxf(E2 - m * m, 0.f) + 1e-5f);

    float4 wA = *(const float4*)(W + 2 * j);
    float4 wB = *(const float4*)(W + 2 * j + 4);
    float4 bb = *(const float4*)(bv + j);
    float4 gg = *(const float4*)(gam + j);
    float4 ee = *(const float4*)(bet + j);

    float y[4];
    y[0] = x0 * wA.x + x1 * wA.y + bb.x;
    y[1] = x0 * wA.z + x1 * wA.w + bb.y;
    y[2] = x0 * wB.x + x1 * wB.y + bb.z;
    y[3] = x0 * wB.z + x1 * wB.w + bb.w;
    float gv[4] = {gg.x, gg.y, gg.z, gg.w};
    float ev[4] = {ee.x, ee.y, ee.z, ee.w};

    bf16 h[4], l[4];
#pragma unroll
    for (int q = 0; q < 4; q++) {
        float t = (y[q] - m) * rstd * gv[q] + ev[q];
        float o;
        if (act == 0) o = 0.5f * t * (1.0f + erff(t * 0.70710678118654752f));
        else          o = t / (1.0f + expf(-t));
        h[q] = __float2bfloat16(o);
        l[q] = __float2bfloat16(o - __bfloat162float(h[q]));
    }
    size_t base = (size_t)b * N + j;
    __nv_bfloat162 h01; h01.x = h[0]; h01.y = h[1];
    __nv_bfloat162 h23; h23.x = h[2]; h23.y = h[3];
    __nv_bfloat162 l01; l01.x = l[0]; l01.y = l[1];
    __nv_bfloat162 l23; l23.x = l[2]; l23.y = l[3];
    *(__nv_bfloat162*)(ohi + base)     = h01;
    *(__nv_bfloat162*)(ohi + base + 2) = h23;
    *(__nv_bfloat162*)(olo + base)     = l01;
    *(__nv_bfloat162*)(olo + base + 2) = l23;
}

// ---------------------------------------------------------------------------
// Row LayerNorm + tanh over N=2048, fp32 in -> bf16 hi/lo out
// ---------------------------------------------------------------------------
__global__ void ln_tanh_rows(const float* __restrict__ data,
                             const float* __restrict__ gam, const float* __restrict__ bet,
                             bf16* __restrict__ ohi, bf16* __restrict__ olo) {
    const int N = 2048;
    int row = blockIdx.x, tid = threadIdx.x;
    const float* p = data + (size_t)row * N;

    float v[8], s = 0.f, s2 = 0.f;
#pragma unroll
    for (int i = 0; i < 8; i++) {
        float t = p[tid + i * 256];
        v[i] = t; s += t; s2 += t * t;
    }
#pragma unroll
    for (int o = 16; o > 0; o >>= 1) {
        s  += __shfl_down_sync(0xffffffffu, s, o);
        s2 += __shfl_down_sync(0xffffffffu, s2, o);
    }
    __shared__ float sh[2][8];
    __shared__ float mb[2];
    int w = tid >> 5, l = tid & 31;
    if (l == 0) { sh[0][w] = s; sh[1][w] = s2; }
    __syncthreads();
    if (tid == 0) {
        float S = 0.f, S2 = 0.f;
#pragma unroll
        for (int q = 0; q < 8; q++) { S += sh[0][q]; S2 += sh[1][q]; }
        float mean = S / N;
        mb[0] = mean;
        mb[1] = rsqrtf(fmaxf(S2 / N - mean * mean, 0.f) + 1e-5f);
    }
    __syncthreads();
    float mean = mb[0], rstd = mb[1];
    size_t base = (size_t)row * N;
#pragma unroll
    for (int i = 0; i < 8; i++) {
        int c = tid + i * 256;
        float t = tanhf((v[i] - mean) * rstd * gam[c] + bet[c]);
        bf16 h = __float2bfloat16(t);
        ohi[base + c] = h;
        olo[base + c] = __float2bfloat16(t - __bfloat162float(h));
    }
}

// ---------------------------------------------------------------------------
// qs mix, fp32 amp/phase in -> bf16 hi/lo out
// ---------------------------------------------------------------------------
__global__ void qs_kernel(const float* __restrict__ amp, const float* __restrict__ phase,
                          const float* __restrict__ rot_freq, const float* __restrict__ rot_phase,
                          bf16* __restrict__ qhi, bf16* __restrict__ qlo) {
    int i = blockIdx.x * blockDim.x + threadIdx.x;
    if (i >= BATCH * (QDIM / 4)) return;
    int j = (i & (QDIM / 4 - 1)) << 2;
    float4 a  = *(const float4*)(amp + (size_t)i * 4);
    float4 ph = *(const float4*)(phase + (size_t)i * 4);
    const float* rf = rot_freq  + (size_t)(4 * QDIM + j) * 3;
    const float* rp = rot_phase + (size_t)(4 * QDIM + j) * 3;
    float av[4] = {a.x, a.y, a.z, a.w};
    float pv[4] = {ph.x, ph.y, ph.z, ph.w};
    bf16 h[4], l[4];
#pragma unroll
    for (int q = 0; q < 4; q++) {
        float rx = sinf(av[q] * rf[3 * q + 0] + rp[3 * q + 0]);
        float ry = cosf(pv[q] * rf[3 * q + 1] + rp[3 * q + 1]);
        float rz = tanhf(rp[3 * q + 2]);
        float o = (rx + ry + rz) * (1.0f / 3.0f);
        h[q] = __float2bfloat16(o);
        l[q] = __float2bfloat16(o - __bfloat162float(h[q]));
    }
    __nv_bfloat162 h01; h01.x = h[0]; h01.y = h[1];
    __nv_bfloat162 h23; h23.x = h[2]; h23.y = h[3];
    __nv_bfloat162 l01; l01.x = l[0]; l01.y = l[1];
    __nv_bfloat162 l23; l23.x = l[2]; l23.y = l[3];
    *(__nv_bfloat162*)(qhi + (size_t)i * 4)     = h01;
    *(__nv_bfloat162*)(qhi + (size_t)i * 4 + 2) = h23;
    *(__nv_bfloat162*)(qlo + (size_t)i * 4)     = l01;
    *(__nv_bfloat162*)(qlo + (size_t)i * 4 + 2) = l23;
}

// ---------------------------------------------------------------------------
// Launch
// ---------------------------------------------------------------------------
extern "C" void kernel_launch(void* const* d_in, const int* in_sizes, int n_in,
                              void* d_out, int out_size) {
    const float* x         = (const float*)d_in[0];
    const float* amp_W1    = (const float*)d_in[1];
    const float* amp_b1    = (const float*)d_in[2];
    const float* amp_g1    = (const float*)d_in[3];
    const float* amp_be1   = (const float*)d_in[4];
    const float* amp_W2    = (const float*)d_in[5];
    const float* amp_b2    = (const float*)d_in[6];
    const float* amp_g2    = (const float*)d_in[7];
    const float* amp_be2   = (const float*)d_in[8];
    const float* amp_W3    = (const float*)d_in[9];
    const float* amp_b3    = (const float*)d_in[10];
    const float* ph_W1     = (const float*)d_in[11];
    const float* ph_b1     = (const float*)d_in[12];
    const float* ph_g1     = (const float*)d_in[13];
    const float* ph_be1    = (const float*)d_in[14];
    const float* ph_W2     = (const float*)d_in[15];
    const float* ph_b2     = (const float*)d_in[16];
    const float* rot_freq  = (const float*)d_in[17];
    const float* rot_phase = (const float*)d_in[18];
    const float* attn_in_w = (const float*)d_in[19];
    const float* attn_in_b = (const float*)d_in[20];
    const float* attn_out_w= (const float*)d_in[21];
    const float* attn_out_b= (const float*)d_in[22];
    float* out = (float*)d_out;

    cudaFuncSetAttribute(gemm_mma<0>, cudaFuncAttributeMaxDynamicSharedMemorySize, SMEM_MMA);
    cudaFuncSetAttribute(gemm_mma<1>, cudaFuncAttributeMaxDynamicSharedMemorySize, SMEM_MMA);
    cudaFuncSetAttribute(gemm_mma<2>, cudaFuncAttributeMaxDynamicSharedMemorySize, SMEM_MMA);

#define SYM(p, s) do { void* _t; cudaGetSymbolAddress(&_t, s); p = (decltype(p))_t; } while (0)
    bf16 *h1h, *h1l, *h2th, *h2tl, *ph_, *pl_, *qsh, *qsl, *vh, *vl;
    bf16 *w2h, *w2l, *w3h, *w3l, *pw2h, *pw2l, *wvh, *wvl, *woh, *wol;
    float *h2, *amp, *phs;
    SYM(h1h, g_h1h);  SYM(h1l, g_h1l);
    SYM(h2, g_h2);    SYM(h2th, g_h2th); SYM(h2tl, g_h2tl);
    SYM(ph_, g_ph);   SYM(pl_, g_pl);
    SYM(amp, g_amp);  SYM(phs, g_phs);
    SYM(qsh, g_qsh);  SYM(qsl, g_qsl);
    SYM(vh, g_vh);    SYM(vl, g_vl);
    SYM(w2h, g_w2h);  SYM(w2l, g_w2l);
    SYM(w3h, g_w3h);  SYM(w3l, g_w3l);
    SYM(pw2h, g_pw2h);SYM(pw2l, g_pw2l);
    SYM(wvh, g_wvh);  SYM(wvl, g_wvl);
    SYM(woh, g_woh);  SYM(wol, g_wol);
#undef SYM

    // moments for closed-form LN of the F=2 layers
    moments_kernel<<<1, 256>>>(amp_W1, amp_b1, N1, 0);
    moments_kernel<<<1, 256>>>(ph_W1,  ph_b1,  N2, 1);

    // weight splits
    {
        int n4;
        n4 = N2 * N1 / 4;     split_fp32<<<(n4 + 255) / 256, 256>>>(amp_W2, w2h, w2l, n4);
        n4 = QDIM * N2 / 4;   split_fp32<<<(n4 + 255) / 256, 256>>>(amp_W3, w3h, w3l, n4);
        n4 = QDIM * N2 / 4;   split_fp32<<<(n4 + 255) / 256, 256>>>(ph_W2, pw2h, pw2l, n4);
        n4 = QDIM * QDIM / 4; split_fp32<<<(n4 + 255) / 256, 256>>>(
            attn_in_w + (size_t)2 * QDIM * QDIM, wvh, wvl, n4);
        n4 = QDIM * QDIM / 4; split_fp32<<<(n4 + 255) / 256, 256>>>(attn_out_w, woh, wol, n4);
    }

    // layer-1 both branches (elementwise, bf16-split outputs)
    layer1_kernel<<<(BATCH * (N1 / 4) + 255) / 256, 256>>>(
        x, amp_W1, amp_b1, amp_g1, amp_be1, h1h, h1l, N1, 0, 0);
    layer1_kernel<<<(BATCH * (N2 / 4) + 255) / 256, 256>>>(
        x, ph_W1, ph_b1, ph_g1, ph_be1, ph_, pl_, N2, 1, 1);

    // GEMM1: h2 = h1 @ W2^T + b2 (fp32 out)
    gemm_mma<0><<<dim3(N2 / BN, BATCH / BM), 256, SMEM_MMA>>>(
        h1h, h1l, w2h, w2l, amp_b2, h2, nullptr, nullptr, N2, N1);
    // LN + tanh -> bf16 split
    ln_tanh_rows<<<BATCH, 256>>>(h2, amp_g2, amp_be2, h2th, h2tl);
    // GEMM2: amp = h2t @ W3^T + b3
    gemm_mma<0><<<dim3(QDIM / BN, BATCH / BM), 256, SMEM_MMA>>>(
        h2th, h2tl, w3h, w3l, amp_b3, amp, nullptr, nullptr, QDIM, N2);
    // GEMM3: phase = tanh(p @ phW2^T + b2)
    gemm_mma<1><<<dim3(QDIM / BN, BATCH / BM), 256, SMEM_MMA>>>(
        ph_, pl_, pw2h, pw2l, ph_b2, phs, nullptr, nullptr, QDIM, N2);
    // qs mix -> bf16 split
    qs_kernel<<<(BATCH * (QDIM / 4) + 255) / 256, 256>>>(amp, phs, rot_freq, rot_phase, qsh, qsl);
    // GEMM4: v = qs @ Wv^T + bv (bf16-split out)
    gemm_mma<2><<<dim3(QDIM / BN, BATCH / BM), 256, SMEM_MMA>>>(
        qsh, qsl, wvh, wvl, attn_in_b + 2 * QDIM, nullptr, vh, vl, QDIM, QDIM);
    // GEMM5: out = v @ Wout^T + bout
    gemm_mma<0><<<dim3(QDIM / BN, BATCH / BM), 256, SMEM_MMA>>>(
        vh, vl, woh, wol, attn_out_b, out, nullptr, nullptr, QDIM, QDIM);
}

// round 11
// speedup vs baseline: 3.1555x; 1.2920x over previous
#include <cuda_runtime.h>
#include <cuda_bf16.h>
#include <math.h>
#include <stdint.h>

#define BATCH 16384
#define QDIM  1024
#define N1    4096
#define N2    2048

typedef __nv_bfloat16 bf16;

// ---------------------------------------------------------------------------
// Scratch (device globals — allocation-free rule)
// ---------------------------------------------------------------------------
__device__ float g_stats[2][9];
__device__ bf16  g_h1h[(size_t)BATCH * N1];
__device__ bf16  g_h1l[(size_t)BATCH * N1];
__device__ float g_h2 [(size_t)BATCH * N2];
__device__ bf16  g_h2th[(size_t)BATCH * N2];
__device__ bf16  g_h2tl[(size_t)BATCH * N2];
__device__ bf16  g_ph [(size_t)BATCH * N2];
__device__ bf16  g_pl [(size_t)BATCH * N2];
__device__ float g_amp[(size_t)BATCH * QDIM];
__device__ float g_phs[(size_t)BATCH * QDIM];
__device__ bf16  g_qsh[(size_t)BATCH * QDIM];
__device__ bf16  g_qsl[(size_t)BATCH * QDIM];
__device__ bf16  g_vh [(size_t)BATCH * QDIM];
__device__ bf16  g_vl [(size_t)BATCH * QDIM];
__device__ bf16  g_w2h[(size_t)N2 * N1],  g_w2l[(size_t)N2 * N1];
__device__ bf16  g_w3h[(size_t)QDIM * N2], g_w3l[(size_t)QDIM * N2];
__device__ bf16  g_pw2h[(size_t)QDIM * N2], g_pw2l[(size_t)QDIM * N2];
__device__ bf16  g_wvh[(size_t)QDIM * QDIM], g_wvl[(size_t)QDIM * QDIM];
__device__ bf16  g_woh[(size_t)QDIM * QDIM], g_wol[(size_t)QDIM * QDIM];

// ---------------------------------------------------------------------------
// Helpers
// ---------------------------------------------------------------------------
__device__ __forceinline__ uint32_t smem_u32(const void* p) {
    uint32_t a;
    asm("{ .reg .u64 t; cvta.to.shared.u64 t, %1; cvt.u32.u64 %0, t; }"
        : "=r"(a) : "l"(p));
    return a;
}
__device__ __forceinline__ size_t gaddr(const void* p) {
    size_t r;
    asm("cvta.to.global.u64 %0, %1;" : "=l"(r) : "l"(p));
    return r;
}
static __device__ __forceinline__ uint32_t swz128(uint32_t x) {
    return x ^ ((x >> 3) & 0x70);
}

// ---------------------------------------------------------------------------
// Fused split-precision bf16 GEMM via mma.sync (HMMA):
//   C[M,N] = (Ah+Al)[M,K] @ (Bh+Bl)[N,K]^T + bias   (Al*Bl dropped)
// All three passes (Ah*Bh, Al*Bh, Ah*Bl) fused into ONE K-loop: 4 tiles
// (Ah|Al|Bh|Bl) staged per BK=64 chunk, fragments reused across passes.
// 2x less global/smem traffic and 1.5x fewer ldmatrix than the phased form.
// CTA 128x128, 8 warps (64x32 warp tiles), 3-stage cp.async ring (192 KB).
// EPI: 0 = fp32 out, 1 = tanh fp32 out, 2 = bf16 hi/lo split out.
// ---------------------------------------------------------------------------
#define BM 128
#define BN 128
#define BK 64
#define TILE_B (BM * BK * 2)       // 16384 bytes per tile
#define STG_B  (4 * TILE_B)        // 65536: Ah | Al | Bh | Bl
#define NSTG   3
#define SMEM_F (NSTG * STG_B)      // 196608

template <int EPI>
__global__ __launch_bounds__(256, 1)
void gemm_fused(const bf16* __restrict__ Ah, const bf16* __restrict__ Al,
                const bf16* __restrict__ Bh, const bf16* __restrict__ Bl,
                const float* __restrict__ bias,
                float* __restrict__ Cf, bf16* __restrict__ Chi, bf16* __restrict__ Clo,
                int Ntot, int K) {
    extern __shared__ char smem[];
    uint32_t sbase = smem_u32(smem);
    int tid = threadIdx.x, lane = tid & 31, wid = tid >> 5;
    int bm = blockIdx.y * BM, bn = blockIdx.x * BN;
    int wm = (wid >> 2) * 64, wn = (wid & 3) * 32;

    const int nIt = K / BK;

    float acc[16][4];
#pragma unroll
    for (int i = 0; i < 16; i++)
#pragma unroll
        for (int j = 0; j < 4; j++) acc[i][j] = 0.f;

    int lrow = tid >> 3;        // 0..31 base row; +32*i
    int lcol = (tid & 7) * 16;  // byte column within 128B row

    auto issue_stage = [&](int it, int stage) {
        uint32_t sb = sbase + stage * STG_B;
        int kb = it * BK + (tid & 7) * 8;   // element offset in K
#pragma unroll
        for (int i = 0; i < 4; i++) {
            int row = lrow + i * 32;
            uint32_t off = swz128((uint32_t)(row * 128 + lcol));
            size_t grA = (size_t)(bm + row) * K + kb;
            size_t grB = (size_t)(bn + row) * K + kb;
            size_t g0 = gaddr(Ah + grA);
            size_t g1 = gaddr(Al + grA);
            size_t g2 = gaddr(Bh + grB);
            size_t g3 = gaddr(Bl + grB);
            asm volatile("cp.async.cg.shared.global [%0], [%1], 16;"
                         :: "r"(sb + off), "l"(g0));
            asm volatile("cp.async.cg.shared.global [%0], [%1], 16;"
                         :: "r"(sb + TILE_B + off), "l"(g1));
            asm volatile("cp.async.cg.shared.global [%0], [%1], 16;"
                         :: "r"(sb + 2 * TILE_B + off), "l"(g2));
            asm volatile("cp.async.cg.shared.global [%0], [%1], 16;"
                         :: "r"(sb + 3 * TILE_B + off), "l"(g3));
        }
        asm volatile("cp.async.commit_group;" ::: "memory");
    };

    // prologue: 2 stages in flight
    issue_stage(0, 0);
    if (nIt > 1) issue_stage(1, 1);

    for (int it = 0; it < nIt; it++) {
        if (it + 1 < nIt) {
            asm volatile("cp.async.wait_group 1;" ::: "memory");
        } else {
            asm volatile("cp.async.wait_group 0;" ::: "memory");
        }
        __syncthreads();
        if (it + 2 < nIt) issue_stage(it + 2, (it + 2) % NSTG);

        uint32_t sb  = sbase + (it % NSTG) * STG_B;
        uint32_t sAh = sb, sAl = sb + TILE_B;
        uint32_t sBh = sb + 2 * TILE_B, sBl = sb + 3 * TILE_B;

#pragma unroll
        for (int ks = 0; ks < 4; ks++) {
            uint32_t ah[4][4], al[4][4], bh[4][2], bl[4][2];
#pragma unroll
            for (int mi = 0; mi < 4; mi++) {
                int row = wm + mi * 16 + (lane & 15);
                uint32_t off = swz128((uint32_t)(row * 128 + ks * 32 + (lane >> 4) * 16));
                asm volatile("ldmatrix.sync.aligned.m8n8.x4.shared.b16 {%0,%1,%2,%3}, [%4];"
                             : "=r"(ah[mi][0]), "=r"(ah[mi][1]), "=r"(ah[mi][2]), "=r"(ah[mi][3])
                             : "r"(sAh + off));
                asm volatile("ldmatrix.sync.aligned.m8n8.x4.shared.b16 {%0,%1,%2,%3}, [%4];"
                             : "=r"(al[mi][0]), "=r"(al[mi][1]), "=r"(al[mi][2]), "=r"(al[mi][3])
                             : "r"(sAl + off));
            }
#pragma unroll
            for (int ni = 0; ni < 4; ni++) {
                int row = wn + ni * 8 + (lane & 7);
                uint32_t off = swz128((uint32_t)(row * 128 + ks * 32 + ((lane >> 3) & 1) * 16));
                asm volatile("ldmatrix.sync.aligned.m8n8.x2.shared.b16 {%0,%1}, [%2];"
                             : "=r"(bh[ni][0]), "=r"(bh[ni][1]) : "r"(sBh + off));
                asm volatile("ldmatrix.sync.aligned.m8n8.x2.shared.b16 {%0,%1}, [%2];"
                             : "=r"(bl[ni][0]), "=r"(bl[ni][1]) : "r"(sBl + off));
            }
#define MMA_B(Areg, Breg)                                                      \
            _Pragma("unroll")                                                  \
            for (int mi = 0; mi < 4; mi++)                                     \
                _Pragma("unroll")                                              \
                for (int ni = 0; ni < 4; ni++) {                               \
                    float* c = acc[mi * 4 + ni];                               \
                    asm volatile(                                              \
                        "mma.sync.aligned.m16n8k16.row.col.f32.bf16.bf16.f32 " \
                        "{%0,%1,%2,%3}, {%4,%5,%6,%7}, {%8,%9}, {%0,%1,%2,%3};"\
                        : "+f"(c[0]), "+f"(c[1]), "+f"(c[2]), "+f"(c[3])       \
                        : "r"(Areg[mi][0]), "r"(Areg[mi][1]),                  \
                          "r"(Areg[mi][2]), "r"(Areg[mi][3]),                  \
                          "r"(Breg[ni][0]), "r"(Breg[ni][1]));                 \
                }
            MMA_B(ah, bh)
            MMA_B(al, bh)
            MMA_B(ah, bl)
#undef MMA_B
        }
        __syncthreads();
    }

    // epilogue (same layout as proven R4 kernel)
    int mb = bm + wm, nb = bn + wn;
#pragma unroll
    for (int mi = 0; mi < 4; mi++)
#pragma unroll
        for (int ni = 0; ni < 4; ni++) {
            float* c = acc[mi * 4 + ni];
            int r0 = mb + mi * 16 + (lane >> 2);
            int c0 = nb + ni * 8 + (lane & 3) * 2;
            float b0 = __ldg(bias + c0), b1 = __ldg(bias + c0 + 1);
            float y0 = c[0] + b0, y1 = c[1] + b1;
            float y2 = c[2] + b0, y3 = c[3] + b1;
            if (EPI == 1) {
                y0 = tanhf(y0); y1 = tanhf(y1); y2 = tanhf(y2); y3 = tanhf(y3);
            }
            if (EPI == 2) {
                bf16 h0 = __float2bfloat16(y0), h1 = __float2bfloat16(y1);
                bf16 h2 = __float2bfloat16(y2), h3 = __float2bfloat16(y3);
                __nv_bfloat162 hh0; hh0.x = h0; hh0.y = h1;
                __nv_bfloat162 hh1; hh1.x = h2; hh1.y = h3;
                __nv_bfloat162 ll0;
                ll0.x = __float2bfloat16(y0 - __bfloat162float(h0));
                ll0.y = __float2bfloat16(y1 - __bfloat162float(h1));
                __nv_bfloat162 ll1;
                ll1.x = __float2bfloat16(y2 - __bfloat162float(h2));
                ll1.y = __float2bfloat16(y3 - __bfloat162float(h3));
                *(__nv_bfloat162*)(Chi + (size_t)r0 * Ntot + c0)       = hh0;
                *(__nv_bfloat162*)(Chi + (size_t)(r0 + 8) * Ntot + c0) = hh1;
                *(__nv_bfloat162*)(Clo + (size_t)r0 * Ntot + c0)       = ll0;
                *(__nv_bfloat162*)(Clo + (size_t)(r0 + 8) * Ntot + c0) = ll1;
            } else {
                *(float2*)(Cf + (size_t)r0 * Ntot + c0)       = make_float2(y0, y1);
                *(float2*)(Cf + (size_t)(r0 + 8) * Ntot + c0) = make_float2(y2, y3);
            }
        }
}

// ---------------------------------------------------------------------------
// Weight split: fp32 -> bf16 hi + bf16 lo
// ---------------------------------------------------------------------------
__global__ void split_fp32(const float* __restrict__ in, bf16* __restrict__ hi,
                           bf16* __restrict__ lo, int n4) {
    int i = blockIdx.x * blockDim.x + threadIdx.x;
    if (i >= n4) return;
    float4 v = *(const float4*)(in + 4 * i);
    float xv[4] = {v.x, v.y, v.z, v.w};
    bf16 h[4], l[4];
#pragma unroll
    for (int q = 0; q < 4; q++) {
        h[q] = __float2bfloat16(xv[q]);
        l[q] = __float2bfloat16(xv[q] - __bfloat162float(h[q]));
    }
    __nv_bfloat162 h01; h01.x = h[0]; h01.y = h[1];
    __nv_bfloat162 h23; h23.x = h[2]; h23.y = h[3];
    __nv_bfloat162 l01; l01.x = l[0]; l01.y = l[1];
    __nv_bfloat162 l23; l23.x = l[2]; l23.y = l[3];
    *(__nv_bfloat162*)(hi + 4 * i)     = h01;
    *(__nv_bfloat162*)(hi + 4 * i + 2) = h23;
    *(__nv_bfloat162*)(lo + 4 * i)     = l01;
    *(__nv_bfloat162*)(lo + 4 * i + 2) = l23;
}

// ---------------------------------------------------------------------------
// Moments for the F=2 closed-form LN
// ---------------------------------------------------------------------------
__global__ void moments_kernel(const float* __restrict__ W,
                               const float* __restrict__ bv, int N, int which) {
    int tid = threadIdx.x;
    double acc[9];
#pragma unroll
    for (int q = 0; q < 9; q++) acc[q] = 0.0;
    for (int j = tid; j < N; j += 256) {
        double w0 = W[2 * j], w1 = W[2 * j + 1], b = bv[j];
        acc[0] += w0;      acc[1] += w1;      acc[2] += b;
        acc[3] += w0 * w0; acc[4] += w1 * w1; acc[5] += b * b;
        acc[6] += w0 * w1; acc[7] += w0 * b;  acc[8] += w1 * b;
    }
    __shared__ double sd[256];
    for (int q = 0; q < 9; q++) {
        sd[tid] = acc[q];
        __syncthreads();
        for (int s = 128; s > 0; s >>= 1) {
            if (tid < s) sd[tid] += sd[tid + s];
            __syncthreads();
        }
        if (tid == 0) g_stats[which][q] = (float)(sd[0] / N);
        __syncthreads();
    }
}

// ---------------------------------------------------------------------------
// Layer-1 (elementwise, closed-form LN) -> bf16 hi/lo. act: 0=gelu, 1=silu
// ---------------------------------------------------------------------------
__global__ void layer1_kernel(const float* __restrict__ x, const float* __restrict__ W,
                              const float* __restrict__ bv, const float* __restrict__ gam,
                              const float* __restrict__ bet,
                              bf16* __restrict__ ohi, bf16* __restrict__ olo,
                              int N, int which, int act) {
    int nv = N >> 2;
    int i = blockIdx.x * blockDim.x + threadIdx.x;
    if (i >= BATCH * nv) return;
    int b = i / nv;
    int j = (i - b * nv) << 2;

    float x0 = __ldg(x + 2 * b), x1 = __ldg(x + 2 * b + 1);
    const float* s = g_stats[which];
    float m  = x0 * s[0] + x1 * s[1] + s[2];
    float E2 = x0 * x0 * s[3] + x1 * x1 * s[4] + s[5]
             + 2.f * (x0 * x1 * s[6] + x0 * s[7] + x1 * s[8]);
    float rstd = rsqrtf(fmaxf(E2 - m * m, 0.f) + 1e-5f);

    float4 wA = *(const float4*)(W + 2 * j);
    float4 wB = *(const float4*)(W + 2 * j + 4);
    float4 bb = *(const float4*)(bv + j);
    float4 gg = *(const float4*)(gam + j);
    float4 ee = *(const float4*)(bet + j);

    float y[4];
    y[0] = x0 * wA.x + x1 * wA.y + bb.x;
    y[1] = x0 * wA.z + x1 * wA.w + bb.y;
    y[2] = x0 * wB.x + x1 * wB.y + bb.z;
    y[3] = x0 * wB.z + x1 * wB.w + bb.w;
    float gv[4] = {gg.x, gg.y, gg.z, gg.w};
    float ev[4] = {ee.x, ee.y, ee.z, ee.w};

    bf16 h[4], l[4];
#pragma unroll
    for (int q = 0; q < 4; q++) {
        float t = (y[q] - m) * rstd * gv[q] + ev[q];
        float o;
        if (act == 0) o = 0.5f * t * (1.0f + erff(t * 0.70710678118654752f));
        else          o = t / (1.0f + expf(-t));
        h[q] = __float2bfloat16(o);
        l[q] = __float2bfloat16(o - __bfloat162float(h[q]));
    }
    size_t base = (size_t)b * N + j;
    __nv_bfloat162 h01; h01.x = h[0]; h01.y = h[1];
    __nv_bfloat162 h23; h23.x = h[2]; h23.y = h[3];
    __nv_bfloat162 l01; l01.x = l[0]; l01.y = l[1];
    __nv_bfloat162 l23; l23.x = l[2]; l23.y = l[3];
    *(__nv_bfloat162*)(ohi + base)     = h01;
    *(__nv_bfloat162*)(ohi + base + 2) = h23;
    *(__nv_bfloat162*)(olo + base)     = l01;
    *(__nv_bfloat162*)(olo + base + 2) = l23;
}

// ---------------------------------------------------------------------------
// Row LayerNorm + tanh over N=2048, fp32 in -> bf16 hi/lo out
// ---------------------------------------------------------------------------
__global__ void ln_tanh_rows(const float* __restrict__ data,
                             const float* __restrict__ gam, const float* __restrict__ bet,
                             bf16* __restrict__ ohi, bf16* __restrict__ olo) {
    const int N = 2048;
    int row = blockIdx.x, tid = threadIdx.x;
    const float* p = data + (size_t)row * N;

    float v[8], s = 0.f, s2 = 0.f;
#pragma unroll
    for (int i = 0; i < 8; i++) {
        float t = p[tid + i * 256];
        v[i] = t; s += t; s2 += t * t;
    }
#pragma unroll
    for (int o = 16; o > 0; o >>= 1) {
        s  += __shfl_down_sync(0xffffffffu, s, o);
        s2 += __shfl_down_sync(0xffffffffu, s2, o);
    }
    __shared__ float sh[2][8];
    __shared__ float mb[2];
    int w = tid >> 5, l = tid & 31;
    if (l == 0) { sh[0][w] = s; sh[1][w] = s2; }
    __syncthreads();
    if (tid == 0) {
        float S = 0.f, S2 = 0.f;
#pragma unroll
        for (int q = 0; q < 8; q++) { S += sh[0][q]; S2 += sh[1][q]; }
        float mean = S / N;
        mb[0] = mean;
        mb[1] = rsqrtf(fmaxf(S2 / N - mean * mean, 0.f) + 1e-5f);
    }
    __syncthreads();
    float mean = mb[0], rstd = mb[1];
    size_t base = (size_t)row * N;
#pragma unroll
    for (int i = 0; i < 8; i++) {
        int c = tid + i * 256;
        float t = tanhf((v[i] - mean) * rstd * gam[c] + bet[c]);
        bf16 h = __float2bfloat16(t);
        ohi[base + c] = h;
        olo[base + c] = __float2bfloat16(t - __bfloat162float(h));
    }
}

// ---------------------------------------------------------------------------
// qs mix, fp32 amp/phase in -> bf16 hi/lo out
// ---------------------------------------------------------------------------
__global__ void qs_kernel(const float* __restrict__ amp, const float* __restrict__ phase,
                          const float* __restrict__ rot_freq, const float* __restrict__ rot_phase,
                          bf16* __restrict__ qhi, bf16* __restrict__ qlo) {
    int i = blockIdx.x * blockDim.x + threadIdx.x;
    if (i >= BATCH * (QDIM / 4)) return;
    int j = (i & (QDIM / 4 - 1)) << 2;
    float4 a  = *(const float4*)(amp + (size_t)i * 4);
    float4 ph = *(const float4*)(phase + (size_t)i * 4);
    const float* rf = rot_freq  + (size_t)(4 * QDIM + j) * 3;
    const float* rp = rot_phase + (size_t)(4 * QDIM + j) * 3;
    float av[4] = {a.x, a.y, a.z, a.w};
    float pv[4] = {ph.x, ph.y, ph.z, ph.w};
    bf16 h[4], l[4];
#pragma unroll
    for (int q = 0; q < 4; q++) {
        float rx = sinf(av[q] * rf[3 * q + 0] + rp[3 * q + 0]);
        float ry = cosf(pv[q] * rf[3 * q + 1] + rp[3 * q + 1]);
        float rz = tanhf(rp[3 * q + 2]);
        float o = (rx + ry + rz) * (1.0f / 3.0f);
        h[q] = __float2bfloat16(o);
        l[q] = __float2bfloat16(o - __bfloat162float(h[q]));
    }
    __nv_bfloat162 h01; h01.x = h[0]; h01.y = h[1];
    __nv_bfloat162 h23; h23.x = h[2]; h23.y = h[3];
    __nv_bfloat162 l01; l01.x = l[0]; l01.y = l[1];
    __nv_bfloat162 l23; l23.x = l[2]; l23.y = l[3];
    *(__nv_bfloat162*)(qhi + (size_t)i * 4)     = h01;
    *(__nv_bfloat162*)(qhi + (size_t)i * 4 + 2) = h23;
    *(__nv_bfloat162*)(qlo + (size_t)i * 4)     = l01;
    *(__nv_bfloat162*)(qlo + (size_t)i * 4 + 2) = l23;
}

// ---------------------------------------------------------------------------
// Launch
// ---------------------------------------------------------------------------
static void gemm_run(int epi,
                     const bf16* Ah, const bf16* Al, const bf16* Bh, const bf16* Bl,
                     const float* bias, float* Cf, bf16* Chi, bf16* Clo,
                     int Ntot, int K) {
    dim3 g(Ntot / BN, BATCH / BM);
    switch (epi) {
    case 0:  gemm_fused<0><<<g, 256, SMEM_F>>>(Ah, Al, Bh, Bl, bias, Cf, Chi, Clo, Ntot, K); break;
    case 1:  gemm_fused<1><<<g, 256, SMEM_F>>>(Ah, Al, Bh, Bl, bias, Cf, Chi, Clo, Ntot, K); break;
    default: gemm_fused<2><<<g, 256, SMEM_F>>>(Ah, Al, Bh, Bl, bias, Cf, Chi, Clo, Ntot, K); break;
    }
}

extern "C" void kernel_launch(void* const* d_in, const int* in_sizes, int n_in,
                              void* d_out, int out_size) {
    const float* x         = (const float*)d_in[0];
    const float* amp_W1    = (const float*)d_in[1];
    const float* amp_b1    = (const float*)d_in[2];
    const float* amp_g1    = (const float*)d_in[3];
    const float* amp_be1   = (const float*)d_in[4];
    const float* amp_W2    = (const float*)d_in[5];
    const float* amp_b2    = (const float*)d_in[6];
    const float* amp_g2    = (const float*)d_in[7];
    const float* amp_be2   = (const float*)d_in[8];
    const float* amp_W3    = (const float*)d_in[9];
    const float* amp_b3    = (const float*)d_in[10];
    const float* ph_W1     = (const float*)d_in[11];
    const float* ph_b1     = (const float*)d_in[12];
    const float* ph_g1     = (const float*)d_in[13];
    const float* ph_be1    = (const float*)d_in[14];
    const float* ph_W2     = (const float*)d_in[15];
    const float* ph_b2     = (const float*)d_in[16];
    const float* rot_freq  = (const float*)d_in[17];
    const float* rot_phase = (const float*)d_in[18];
    const float* attn_in_w = (const float*)d_in[19];
    const float* attn_in_b = (const float*)d_in[20];
    const float* attn_out_w= (const float*)d_in[21];
    const float* attn_out_b= (const float*)d_in[22];
    float* out = (float*)d_out;

    cudaFuncSetAttribute(gemm_fused<0>, cudaFuncAttributeMaxDynamicSharedMemorySize, SMEM_F);
    cudaFuncSetAttribute(gemm_fused<1>, cudaFuncAttributeMaxDynamicSharedMemorySize, SMEM_F);
    cudaFuncSetAttribute(gemm_fused<2>, cudaFuncAttributeMaxDynamicSharedMemorySize, SMEM_F);

#define SYM(p, s) do { void* _t; cudaGetSymbolAddress(&_t, s); p = (decltype(p))_t; } while (0)
    bf16 *h1h, *h1l, *h2th, *h2tl, *ph_, *pl_, *qsh, *qsl, *vh, *vl;
    bf16 *w2h, *w2l, *w3h, *w3l, *pw2h, *pw2l, *wvh, *wvl, *woh, *wol;
    float *h2, *amp, *phs;
    SYM(h1h, g_h1h);  SYM(h1l, g_h1l);
    SYM(h2, g_h2);    SYM(h2th, g_h2th); SYM(h2tl, g_h2tl);
    SYM(ph_, g_ph);   SYM(pl_, g_pl);
    SYM(amp, g_amp);  SYM(phs, g_phs);
    SYM(qsh, g_qsh);  SYM(qsl, g_qsl);
    SYM(vh, g_vh);    SYM(vl, g_vl);
    SYM(w2h, g_w2h);  SYM(w2l, g_w2l);
    SYM(w3h, g_w3h);  SYM(w3l, g_w3l);
    SYM(pw2h, g_pw2h);SYM(pw2l, g_pw2l);
    SYM(wvh, g_wvh);  SYM(wvl, g_wvl);
    SYM(woh, g_woh);  SYM(wol, g_wol);
#undef SYM

    moments_kernel<<<1, 256>>>(amp_W1, amp_b1, N1, 0);
    moments_kernel<<<1, 256>>>(ph_W1,  ph_b1,  N2, 1);

    {
        int n4;
        n4 = N2 * N1 / 4;     split_fp32<<<(n4 + 255) / 256, 256>>>(amp_W2, w2h, w2l, n4);
        n4 = QDIM * N2 / 4;   split_fp32<<<(n4 + 255) / 256, 256>>>(amp_W3, w3h, w3l, n4);
        n4 = QDIM * N2 / 4;   split_fp32<<<(n4 + 255) / 256, 256>>>(ph_W2, pw2h, pw2l, n4);
        n4 = QDIM * QDIM / 4; split_fp32<<<(n4 + 255) / 256, 256>>>(
            attn_in_w + (size_t)2 * QDIM * QDIM, wvh, wvl, n4);
        n4 = QDIM * QDIM / 4; split_fp32<<<(n4 + 255) / 256, 256>>>(attn_out_w, woh, wol, n4);
    }

    layer1_kernel<<<(BATCH * (N1 / 4) + 255) / 256, 256>>>(
        x, amp_W1, amp_b1, amp_g1, amp_be1, h1h, h1l, N1, 0, 0);
    layer1_kernel<<<(BATCH * (N2 / 4) + 255) / 256, 256>>>(
        x, ph_W1, ph_b1, ph_g1, ph_be1, ph_, pl_, N2, 1, 1);

    // GEMM1: h2 = h1 @ W2^T + b2 (fp32 out)
    gemm_run(0, h1h, h1l, w2h, w2l, amp_b2, h2, nullptr, nullptr, N2, N1);
    ln_tanh_rows<<<BATCH, 256>>>(h2, amp_g2, amp_be2, h2th, h2tl);
    // GEMM2: amp = h2t @ W3^T + b3
    gemm_run(0, h2th, h2tl, w3h, w3l, amp_b3, amp, nullptr, nullptr, QDIM, N2);
    // GEMM3: phase = tanh(p @ phW2^T + b2)
    gemm_run(1, ph_, pl_, pw2h, pw2l, ph_b2, phs, nullptr, nullptr, QDIM, N2);
    // qs mix
    qs_kernel<<<(BATCH * (QDIM / 4) + 255) / 256, 256>>>(amp, phs, rot_freq, rot_phase, qsh, qsl);
    // GEMM4: v = qs @ Wv^T + bv (bf16-split out)
    gemm_run(2, qsh, qsl, wvh, wvl, attn_in_b + 2 * QDIM, nullptr, vh, vl, QDIM, QDIM);
    // GEMM5: out = v @ Wout^T + bout
    gemm_run(0, vh, vl, woh, wol, attn_out_b, out, nullptr, nullptr, QDIM, QDIM);
}

// round 12
// speedup vs baseline: 6.2748x; 1.9885x over previous
#include <cuda_runtime.h>
#include <cuda_fp16.h>
#include <math.h>
#include <stdint.h>

#define BATCH 16384
#define QDIM  1024
#define N1    4096
#define N2    2048

// ---------------------------------------------------------------------------
// Scratch (device globals — allocation-free rule)
// ---------------------------------------------------------------------------
__device__ float  g_stats[2][9];
__device__ __half g_h1 [(size_t)BATCH * N1];
__device__ float  g_h2 [(size_t)BATCH * N2];
__device__ __half g_h2t[(size_t)BATCH * N2];
__device__ __half g_p  [(size_t)BATCH * N2];
__device__ float  g_amp[(size_t)BATCH * QDIM];
__device__ float  g_phs[(size_t)BATCH * QDIM];
__device__ __half g_qs [(size_t)BATCH * QDIM];
__device__ __half g_v  [(size_t)BATCH * QDIM];
__device__ __half g_w2 [(size_t)N2 * N1];
__device__ __half g_w3 [(size_t)QDIM * N2];
__device__ __half g_pw2[(size_t)QDIM * N2];
__device__ __half g_wv [(size_t)QDIM * QDIM];
__device__ __half g_wo [(size_t)QDIM * QDIM];

// ---------------------------------------------------------------------------
// Helpers
// ---------------------------------------------------------------------------
__device__ __forceinline__ uint32_t smem_u32(const void* p) {
    uint32_t a;
    asm("{ .reg .u64 t; cvta.to.shared.u64 t, %1; cvt.u32.u64 %0, t; }"
        : "=r"(a) : "l"(p));
    return a;
}
__device__ __forceinline__ size_t gaddr(const void* p) {
    size_t r;
    asm("cvta.to.global.u64 %0, %1;" : "=l"(r) : "l"(p));
    return r;
}
static __device__ __forceinline__ uint32_t swz128(uint32_t x) {
    return x ^ ((x >> 3) & 0x70);
}

// ---------------------------------------------------------------------------
// Single-pass fp16 GEMM via mma.sync (HMMA):
//   C[M,N] = A[M,K] @ B[N,K]^T + bias, fp32 accumulate.
// CTA 128x128, 8 warps (64x32 warp tiles), BK=64, 3-stage cp.async ring
// (96 KB -> 2 CTAs/SM). Same proven skeleton as the R10 fused kernel.
// EPI: 0 = fp32 out, 1 = tanh fp32 out, 2 = fp16 out.
// ---------------------------------------------------------------------------
#define BM 128
#define BN 128
#define BK 64
#define TILE_B (BM * BK * 2)       // 16384 bytes per tile
#define STG_B  (2 * TILE_B)        // 32768: A | B
#define NSTG   3
#define SMEM_F (NSTG * STG_B)      // 98304

template <int EPI>
__global__ __launch_bounds__(256)
void gemm_fp16(const __half* __restrict__ A, const __half* __restrict__ B,
               const float* __restrict__ bias,
               float* __restrict__ Cf, __half* __restrict__ Ch,
               int Ntot, int K) {
    extern __shared__ char smem[];
    uint32_t sbase = smem_u32(smem);
    int tid = threadIdx.x, lane = tid & 31, wid = tid >> 5;
    int bm = blockIdx.y * BM, bn = blockIdx.x * BN;
    int wm = (wid >> 2) * 64, wn = (wid & 3) * 32;

    const int nIt = K / BK;

    float acc[16][4];
#pragma unroll
    for (int i = 0; i < 16; i++)
#pragma unroll
        for (int j = 0; j < 4; j++) acc[i][j] = 0.f;

    int lrow = tid >> 3;        // 0..31 base row; +32*i
    int lcol = (tid & 7) * 16;  // byte column within 128B row

    auto issue_stage = [&](int it, int stage) {
        uint32_t sb = sbase + stage * STG_B;
        int kb = it * BK + (tid & 7) * 8;   // element offset in K
#pragma unroll
        for (int i = 0; i < 4; i++) {
            int row = lrow + i * 32;
            uint32_t off = swz128((uint32_t)(row * 128 + lcol));
            size_t g0 = gaddr(A + (size_t)(bm + row) * K + kb);
            size_t g1 = gaddr(B + (size_t)(bn + row) * K + kb);
            asm volatile("cp.async.cg.shared.global [%0], [%1], 16;"
                         :: "r"(sb + off), "l"(g0));
            asm volatile("cp.async.cg.shared.global [%0], [%1], 16;"
                         :: "r"(sb + TILE_B + off), "l"(g1));
        }
        asm volatile("cp.async.commit_group;" ::: "memory");
    };

    issue_stage(0, 0);
    if (nIt > 1) issue_stage(1, 1);

    for (int it = 0; it < nIt; it++) {
        if (it + 1 < nIt) {
            asm volatile("cp.async.wait_group 1;" ::: "memory");
        } else {
            asm volatile("cp.async.wait_group 0;" ::: "memory");
        }
        __syncthreads();
        if (it + 2 < nIt) issue_stage(it + 2, (it + 2) % NSTG);

        uint32_t sA = sbase + (it % NSTG) * STG_B;
        uint32_t sB = sA + TILE_B;

#pragma unroll
        for (int ks = 0; ks < 4; ks++) {
            uint32_t a[4][4], b[4][2];
#pragma unroll
            for (int mi = 0; mi < 4; mi++) {
                int row = wm + mi * 16 + (lane & 15);
                uint32_t off = swz128((uint32_t)(row * 128 + ks * 32 + (lane >> 4) * 16));
                asm volatile("ldmatrix.sync.aligned.m8n8.x4.shared.b16 {%0,%1,%2,%3}, [%4];"
                             : "=r"(a[mi][0]), "=r"(a[mi][1]), "=r"(a[mi][2]), "=r"(a[mi][3])
                             : "r"(sA + off));
            }
#pragma unroll
            for (int ni = 0; ni < 4; ni++) {
                int row = wn + ni * 8 + (lane & 7);
                uint32_t off = swz128((uint32_t)(row * 128 + ks * 32 + ((lane >> 3) & 1) * 16));
                asm volatile("ldmatrix.sync.aligned.m8n8.x2.shared.b16 {%0,%1}, [%2];"
                             : "=r"(b[ni][0]), "=r"(b[ni][1]) : "r"(sB + off));
            }
#pragma unroll
            for (int mi = 0; mi < 4; mi++)
#pragma unroll
                for (int ni = 0; ni < 4; ni++) {
                    float* c = acc[mi * 4 + ni];
                    asm volatile(
                        "mma.sync.aligned.m16n8k16.row.col.f32.f16.f16.f32 "
                        "{%0,%1,%2,%3}, {%4,%5,%6,%7}, {%8,%9}, {%0,%1,%2,%3};"
                        : "+f"(c[0]), "+f"(c[1]), "+f"(c[2]), "+f"(c[3])
                        : "r"(a[mi][0]), "r"(a[mi][1]), "r"(a[mi][2]), "r"(a[mi][3]),
                          "r"(b[ni][0]), "r"(b[ni][1]));
                }
        }
        __syncthreads();
    }

    // epilogue (same fragment->row/col mapping as proven kernels)
    int mb = bm + wm, nb = bn + wn;
#pragma unroll
    for (int mi = 0; mi < 4; mi++)
#pragma unroll
        for (int ni = 0; ni < 4; ni++) {
            float* c = acc[mi * 4 + ni];
            int r0 = mb + mi * 16 + (lane >> 2);
            int c0 = nb + ni * 8 + (lane & 3) * 2;
            float b0 = __ldg(bias + c0), b1 = __ldg(bias + c0 + 1);
            float y0 = c[0] + b0, y1 = c[1] + b1;
            float y2 = c[2] + b0, y3 = c[3] + b1;
            if (EPI == 1) {
                y0 = tanhf(y0); y1 = tanhf(y1); y2 = tanhf(y2); y3 = tanhf(y3);
            }
            if (EPI == 2) {
                __half2 p0; p0.x = __float2half(y0); p0.y = __float2half(y1);
                __half2 p1; p1.x = __float2half(y2); p1.y = __float2half(y3);
                *(__half2*)(Ch + (size_t)r0 * Ntot + c0)       = p0;
                *(__half2*)(Ch + (size_t)(r0 + 8) * Ntot + c0) = p1;
            } else {
                *(float2*)(Cf + (size_t)r0 * Ntot + c0)       = make_float2(y0, y1);
                *(float2*)(Cf + (size_t)(r0 + 8) * Ntot + c0) = make_float2(y2, y3);
            }
        }
}

// ---------------------------------------------------------------------------
// Weight convert: fp32 -> fp16 (8 elems/thread, 16B store)
// ---------------------------------------------------------------------------
__global__ void conv_fp16(const float* __restrict__ in, __half* __restrict__ out, int n8) {
    int i = blockIdx.x * blockDim.x + threadIdx.x;
    if (i >= n8) return;
    float4 v0 = *(const float4*)(in + 8 * i);
    float4 v1 = *(const float4*)(in + 8 * i + 4);
    __half2 h[4];
    h[0].x = __float2half(v0.x); h[0].y = __float2half(v0.y);
    h[1].x = __float2half(v0.z); h[1].y = __float2half(v0.w);
    h[2].x = __float2half(v1.x); h[2].y = __float2half(v1.y);
    h[3].x = __float2half(v1.z); h[3].y = __float2half(v1.w);
    *(uint4*)(out + 8 * i) = *(uint4*)h;
}

// ---------------------------------------------------------------------------
// Moments for the F=2 closed-form LN
// ---------------------------------------------------------------------------
__global__ void moments_kernel(const float* __restrict__ W,
                               const float* __restrict__ bv, int N, int which) {
    int tid = threadIdx.x;
    double acc[9];
#pragma unroll
    for (int q = 0; q < 9; q++) acc[q] = 0.0;
    for (int j = tid; j < N; j += 256) {
        double w0 = W[2 * j], w1 = W[2 * j + 1], b = bv[j];
        acc[0] += w0;      acc[1] += w1;      acc[2] += b;
        acc[3] += w0 * w0; acc[4] += w1 * w1; acc[5] += b * b;
        acc[6] += w0 * w1; acc[7] += w0 * b;  acc[8] += w1 * b;
    }
    __shared__ double sd[256];
    for (int q = 0; q < 9; q++) {
        sd[tid] = acc[q];
        __syncthreads();
        for (int s = 128; s > 0; s >>= 1) {
            if (tid < s) sd[tid] += sd[tid + s];
            __syncthreads();
        }
        if (tid == 0) g_stats[which][q] = (float)(sd[0] / N);
        __syncthreads();
    }
}

// ---------------------------------------------------------------------------
// Layer-1 (elementwise, closed-form LN) -> fp16. act: 0=gelu, 1=silu
// ---------------------------------------------------------------------------
__global__ void layer1_kernel(const float* __restrict__ x, const float* __restrict__ W,
                              const float* __restrict__ bv, const float* __restrict__ gam,
                              const float* __restrict__ bet,
                              __half* __restrict__ oh,
                              int N, int which, int act) {
    int nv = N >> 2;
    int i = blockIdx.x * blockDim.x + threadIdx.x;
    if (i >= BATCH * nv) return;
    int b = i / nv;
    int j = (i - b * nv) << 2;

    float x0 = __ldg(x + 2 * b), x1 = __ldg(x + 2 * b + 1);
    const float* s = g_stats[which];
    float m  = x0 * s[0] + x1 * s[1] + s[2];
    float E2 = x0 * x0 * s[3] + x1 * x1 * s[4] + s[5]
             + 2.f * (x0 * x1 * s[6] + x0 * s[7] + x1 * s[8]);
    float rstd = rsqrtf(fmaxf(E2 - m * m, 0.f) + 1e-5f);

    float4 wA = *(const float4*)(W + 2 * j);
    float4 wB = *(const float4*)(W + 2 * j + 4);
    float4 bb = *(const float4*)(bv + j);
    float4 gg = *(const float4*)(gam + j);
    float4 ee = *(const float4*)(bet + j);

    float y[4];
    y[0] = x0 * wA.x + x1 * wA.y + bb.x;
    y[1] = x0 * wA.z + x1 * wA.w + bb.y;
    y[2] = x0 * wB.x + x1 * wB.y + bb.z;
    y[3] = x0 * wB.z + x1 * wB.w + bb.w;
    float gv[4] = {gg.x, gg.y, gg.z, gg.w};
    float ev[4] = {ee.x, ee.y, ee.z, ee.w};

    __half2 o01, o23;
    float o[4];
#pragma unroll
    for (int q = 0; q < 4; q++) {
        float t = (y[q] - m) * rstd * gv[q] + ev[q];
        if (act == 0) o[q] = 0.5f * t * (1.0f + erff(t * 0.70710678118654752f));
        else          o[q] = t / (1.0f + expf(-t));
    }
    o01.x = __float2half(o[0]); o01.y = __float2half(o[1]);
    o23.x = __float2half(o[2]); o23.y = __float2half(o[3]);
    size_t base = (size_t)b * N + j;
    *(__half2*)(oh + base)     = o01;
    *(__half2*)(oh + base + 2) = o23;
}

// ---------------------------------------------------------------------------
// Row LayerNorm + tanh over N=2048, fp32 in -> fp16 out
// ---------------------------------------------------------------------------
__global__ void ln_tanh_rows(const float* __restrict__ data,
                             const float* __restrict__ gam, const float* __restrict__ bet,
                             __half* __restrict__ oh) {
    const int N = 2048;
    int row = blockIdx.x, tid = threadIdx.x;
    const float* p = data + (size_t)row * N;

    float v[8], s = 0.f, s2 = 0.f;
#pragma unroll
    for (int i = 0; i < 8; i++) {
        float t = p[tid + i * 256];
        v[i] = t; s += t; s2 += t * t;
    }
#pragma unroll
    for (int o = 16; o > 0; o >>= 1) {
        s  += __shfl_down_sync(0xffffffffu, s, o);
        s2 += __shfl_down_sync(0xffffffffu, s2, o);
    }
    __shared__ float sh[2][8];
    __shared__ float mb[2];
    int w = tid >> 5, l = tid & 31;
    if (l == 0) { sh[0][w] = s; sh[1][w] = s2; }
    __syncthreads();
    if (tid == 0) {
        float S = 0.f, S2 = 0.f;
#pragma unroll
        for (int q = 0; q < 8; q++) { S += sh[0][q]; S2 += sh[1][q]; }
        float mean = S / N;
        mb[0] = mean;
        mb[1] = rsqrtf(fmaxf(S2 / N - mean * mean, 0.f) + 1e-5f);
    }
    __syncthreads();
    float mean = mb[0], rstd = mb[1];
    size_t base = (size_t)row * N;
#pragma unroll
    for (int i = 0; i < 8; i++) {
        int c = tid + i * 256;
        float t = tanhf((v[i] - mean) * rstd * gam[c] + bet[c]);
        oh[base + c] = __float2half(t);
    }
}

// ---------------------------------------------------------------------------
// qs mix, fp32 amp/phase in -> fp16 out
// ---------------------------------------------------------------------------
__global__ void qs_kernel(const float* __restrict__ amp, const float* __restrict__ phase,
                          const float* __restrict__ rot_freq, const float* __restrict__ rot_phase,
                          __half* __restrict__ qh) {
    int i = blockIdx.x * blockDim.x + threadIdx.x;
    if (i >= BATCH * (QDIM / 4)) return;
    int j = (i & (QDIM / 4 - 1)) << 2;
    float4 a  = *(const float4*)(amp + (size_t)i * 4);
    float4 ph = *(const float4*)(phase + (size_t)i * 4);
    const float* rf = rot_freq  + (size_t)(4 * QDIM + j) * 3;
    const float* rp = rot_phase + (size_t)(4 * QDIM + j) * 3;
    float av[4] = {a.x, a.y, a.z, a.w};
    float pv[4] = {ph.x, ph.y, ph.z, ph.w};
    float o[4];
#pragma unroll
    for (int q = 0; q < 4; q++) {
        float rx = sinf(av[q] * rf[3 * q + 0] + rp[3 * q + 0]);
        float ry = cosf(pv[q] * rf[3 * q + 1] + rp[3 * q + 1]);
        float rz = tanhf(rp[3 * q + 2]);
        o[q] = (rx + ry + rz) * (1.0f / 3.0f);
    }
    __half2 o01, o23;
    o01.x = __float2half(o[0]); o01.y = __float2half(o[1]);
    o23.x = __float2half(o[2]); o23.y = __float2half(o[3]);
    *(__half2*)(qh + (size_t)i * 4)     = o01;
    *(__half2*)(qh + (size_t)i * 4 + 2) = o23;
}

// ---------------------------------------------------------------------------
// Launch
// ---------------------------------------------------------------------------
static void gemm_run(int epi, const __half* A, const __half* B,
                     const float* bias, float* Cf, __half* Ch, int Ntot, int K) {
    dim3 g(Ntot / BN, BATCH / BM);
    switch (epi) {
    case 0:  gemm_fp16<0><<<g, 256, SMEM_F>>>(A, B, bias, Cf, Ch, Ntot, K); break;
    case 1:  gemm_fp16<1><<<g, 256, SMEM_F>>>(A, B, bias, Cf, Ch, Ntot, K); break;
    default: gemm_fp16<2><<<g, 256, SMEM_F>>>(A, B, bias, Cf, Ch, Ntot, K); break;
    }
}

extern "C" void kernel_launch(void* const* d_in, const int* in_sizes, int n_in,
                              void* d_out, int out_size) {
    const float* x         = (const float*)d_in[0];
    const float* amp_W1    = (const float*)d_in[1];
    const float* amp_b1    = (const float*)d_in[2];
    const float* amp_g1    = (const float*)d_in[3];
    const float* amp_be1   = (const float*)d_in[4];
    const float* amp_W2    = (const float*)d_in[5];
    const float* amp_b2    = (const float*)d_in[6];
    const float* amp_g2    = (const float*)d_in[7];
    const float* amp_be2   = (const float*)d_in[8];
    const float* amp_W3    = (const float*)d_in[9];
    const float* amp_b3    = (const float*)d_in[10];
    const float* ph_W1     = (const float*)d_in[11];
    const float* ph_b1     = (const float*)d_in[12];
    const float* ph_g1     = (const float*)d_in[13];
    const float* ph_be1    = (const float*)d_in[14];
    const float* ph_W2     = (const float*)d_in[15];
    const float* ph_b2     = (const float*)d_in[16];
    const float* rot_freq  = (const float*)d_in[17];
    const float* rot_phase = (const float*)d_in[18];
    const float* attn_in_w = (const float*)d_in[19];
    const float* attn_in_b = (const float*)d_in[20];
    const float* attn_out_w= (const float*)d_in[21];
    const float* attn_out_b= (const float*)d_in[22];
    float* out = (float*)d_out;

    cudaFuncSetAttribute(gemm_fp16<0>, cudaFuncAttributeMaxDynamicSharedMemorySize, SMEM_F);
    cudaFuncSetAttribute(gemm_fp16<1>, cudaFuncAttributeMaxDynamicSharedMemorySize, SMEM_F);
    cudaFuncSetAttribute(gemm_fp16<2>, cudaFuncAttributeMaxDynamicSharedMemorySize, SMEM_F);

#define SYM(p, s) do { void* _t; cudaGetSymbolAddress(&_t, s); p = (decltype(p))_t; } while (0)
    __half *h1, *h2t, *pp, *qs, *v, *w2, *w3, *pw2, *wv, *wo;
    float *h2, *amp, *phs;
    SYM(h1, g_h1);   SYM(h2, g_h2);   SYM(h2t, g_h2t);
    SYM(pp, g_p);    SYM(amp, g_amp); SYM(phs, g_phs);
    SYM(qs, g_qs);   SYM(v, g_v);
    SYM(w2, g_w2);   SYM(w3, g_w3);   SYM(pw2, g_pw2);
    SYM(wv, g_wv);   SYM(wo, g_wo);
#undef SYM

    moments_kernel<<<1, 256>>>(amp_W1, amp_b1, N1, 0);
    moments_kernel<<<1, 256>>>(ph_W1,  ph_b1,  N2, 1);

    {
        int n8;
        n8 = N2 * N1 / 8;     conv_fp16<<<(n8 + 255) / 256, 256>>>(amp_W2, w2, n8);
        n8 = QDIM * N2 / 8;   conv_fp16<<<(n8 + 255) / 256, 256>>>(amp_W3, w3, n8);
        n8 = QDIM * N2 / 8;   conv_fp16<<<(n8 + 255) / 256, 256>>>(ph_W2, pw2, n8);
        n8 = QDIM * QDIM / 8; conv_fp16<<<(n8 + 255) / 256, 256>>>(
            attn_in_w + (size_t)2 * QDIM * QDIM, wv, n8);
        n8 = QDIM * QDIM / 8; conv_fp16<<<(n8 + 255) / 256, 256>>>(attn_out_w, wo, n8);
    }

    layer1_kernel<<<(BATCH * (N1 / 4) + 255) / 256, 256>>>(
        x, amp_W1, amp_b1, amp_g1, amp_be1, h1, N1, 0, 0);
    layer1_kernel<<<(BATCH * (N2 / 4) + 255) / 256, 256>>>(
        x, ph_W1, ph_b1, ph_g1, ph_be1, pp, N2, 1, 1);

    // GEMM1: h2 = h1 @ W2^T + b2 (fp32 out)
    gemm_run(0, h1, w2, amp_b2, h2, nullptr, N2, N1);
    ln_tanh_rows<<<BATCH, 256>>>(h2, amp_g2, amp_be2, h2t);
    // GEMM2: amp = h2t @ W3^T + b3
    gemm_run(0, h2t, w3, amp_b3, amp, nullptr, QDIM, N2);
    // GEMM3: phase = tanh(p @ phW2^T + b2)
    gemm_run(1, pp, pw2, ph_b2, phs, nullptr, QDIM, N2);
    // qs mix
    qs_kernel<<<(BATCH * (QDIM / 4) + 255) / 256, 256>>>(amp, phs, rot_freq, rot_phase, qs);
    // GEMM4: v = qs @ Wv^T + bv (fp16 out)
    gemm_run(2, qs, wv, attn_in_b + 2 * QDIM, nullptr, v, QDIM, QDIM);
    // GEMM5: out = v @ Wout^T + bout
    gemm_run(0, v, wo, attn_out_b, out, nullptr, QDIM, QDIM);
}

// round 13
// speedup vs baseline: 6.6401x; 1.0582x over previous
#include <cuda_runtime.h>
#include <cuda_fp16.h>
#include <math.h>
#include <stdint.h>

#define BATCH 16384
#define QDIM  1024
#define N1    4096
#define N2    2048

// ---------------------------------------------------------------------------
// Scratch (device globals — allocation-free rule)
// ---------------------------------------------------------------------------
__device__ float  g_stats[2][9];
__device__ __half g_h1 [(size_t)BATCH * N1];
__device__ float  g_h2 [(size_t)BATCH * N2];
__device__ __half g_h2t[(size_t)BATCH * N2];
__device__ __half g_p  [(size_t)BATCH * N2];
__device__ float  g_amp[(size_t)BATCH * QDIM];
__device__ float  g_phs[(size_t)BATCH * QDIM];
__device__ __half g_qs [(size_t)BATCH * QDIM];
__device__ __half g_v  [(size_t)BATCH * QDIM];
__device__ __half g_w2 [(size_t)N2 * N1];
__device__ __half g_w3 [(size_t)QDIM * N2];
__device__ __half g_pw2[(size_t)QDIM * N2];
__device__ __half g_wv [(size_t)QDIM * QDIM];
__device__ __half g_wo [(size_t)QDIM * QDIM];

// ---------------------------------------------------------------------------
// Helpers
// ---------------------------------------------------------------------------
__device__ __forceinline__ uint32_t smem_u32(const void* p) {
    uint32_t a;
    asm("{ .reg .u64 t; cvta.to.shared.u64 t, %1; cvt.u32.u64 %0, t; }"
        : "=r"(a) : "l"(p));
    return a;
}
__device__ __forceinline__ size_t gaddr(const void* p) {
    size_t r;
    asm("cvta.to.global.u64 %0, %1;" : "=l"(r) : "l"(p));
    return r;
}
static __device__ __forceinline__ uint32_t swz128(uint32_t x) {
    return x ^ ((x >> 3) & 0x70);
}

// ---------------------------------------------------------------------------
// Single-pass fp16 GEMM via mma.sync (HMMA):
//   C[M,N] = A[M,K] @ B[N,K]^T + bias, fp32 accumulate.
// CTA 128x128, 8 warps (64x32 warp tiles), BK=64, 3-stage cp.async ring
// (96 KB -> 2 CTAs/SM). R12 skeleton + two changes:
//   1) ONE __syncthreads per K-chunk (bottom barrier removed: slot written at
//      iter it == slot read at it-1; top barrier of it already fences that).
//   2) B fragments via ldmatrix.x4 pairing two n-groups (B loads 4 -> 2/ks).
// EPI: 0 = fp32 out, 1 = tanh fp32 out, 2 = fp16 out.
// ---------------------------------------------------------------------------
#define BM 128
#define BN 128
#define BK 64
#define TILE_B (BM * BK * 2)       // 16384 bytes per tile
#define STG_B  (2 * TILE_B)        // 32768: A | B
#define NSTG   3
#define SMEM_F (NSTG * STG_B)      // 98304

template <int EPI>
__global__ __launch_bounds__(256)
void gemm_fp16(const __half* __restrict__ A, const __half* __restrict__ B,
               const float* __restrict__ bias,
               float* __restrict__ Cf, __half* __restrict__ Ch,
               int Ntot, int K) {
    extern __shared__ char smem[];
    uint32_t sbase = smem_u32(smem);
    int tid = threadIdx.x, lane = tid & 31, wid = tid >> 5;
    int bm = blockIdx.y * BM, bn = blockIdx.x * BN;
    int wm = (wid >> 2) * 64, wn = (wid & 3) * 32;

    const int nIt = K / BK;

    float acc[16][4];
#pragma unroll
    for (int i = 0; i < 16; i++)
#pragma unroll
        for (int j = 0; j < 4; j++) acc[i][j] = 0.f;

    int lrow = tid >> 3;        // 0..31 base row; +32*i
    int lcol = (tid & 7) * 16;  // byte column within 128B row

    auto issue_stage = [&](int it, int stage) {
        uint32_t sb = sbase + stage * STG_B;
        int kb = it * BK + (tid & 7) * 8;   // element offset in K
#pragma unroll
        for (int i = 0; i < 4; i++) {
            int row = lrow + i * 32;
            uint32_t off = swz128((uint32_t)(row * 128 + lcol));
            size_t g0 = gaddr(A + (size_t)(bm + row) * K + kb);
            size_t g1 = gaddr(B + (size_t)(bn + row) * K + kb);
            asm volatile("cp.async.cg.shared.global [%0], [%1], 16;"
                         :: "r"(sb + off), "l"(g0));
            asm volatile("cp.async.cg.shared.global [%0], [%1], 16;"
                         :: "r"(sb + TILE_B + off), "l"(g1));
        }
        asm volatile("cp.async.commit_group;" ::: "memory");
    };

    issue_stage(0, 0);
    if (nIt > 1) issue_stage(1, 1);

    for (int it = 0; it < nIt; it++) {
        if (it + 1 < nIt) {
            asm volatile("cp.async.wait_group 1;" ::: "memory");
        } else {
            asm volatile("cp.async.wait_group 0;" ::: "memory");
        }
        __syncthreads();     // stage `it` visible; all threads done with it-1
        if (it + 2 < nIt) issue_stage(it + 2, (it + 2) % NSTG);  // writes slot (it-1)%3 — safe

        uint32_t sA = sbase + (it % NSTG) * STG_B;
        uint32_t sB = sA + TILE_B;

#pragma unroll
        for (int ks = 0; ks < 4; ks++) {
            uint32_t a[4][4], b[4][2];
#pragma unroll
            for (int mi = 0; mi < 4; mi++) {
                int row = wm + mi * 16 + (lane & 15);
                uint32_t off = swz128((uint32_t)(row * 128 + ks * 32 + (lane >> 4) * 16));
                asm volatile("ldmatrix.sync.aligned.m8n8.x4.shared.b16 {%0,%1,%2,%3}, [%4];"
                             : "=r"(a[mi][0]), "=r"(a[mi][1]), "=r"(a[mi][2]), "=r"(a[mi][3])
                             : "r"(sA + off));
            }
            // B: one x4 per pair of n-groups.
            // lanes 0-7: n-group ni, k[0:16)B; 8-15: ni, k[16:32)B;
            // lanes 16-23: ni+1, k[0:16)B; 24-31: ni+1, k[16:32)B.
#pragma unroll
            for (int np = 0; np < 2; np++) {
                int row = wn + np * 16 + ((lane >> 4) & 1) * 8 + (lane & 7);
                uint32_t off = swz128((uint32_t)(row * 128 + ks * 32 + ((lane >> 3) & 1) * 16));
                asm volatile("ldmatrix.sync.aligned.m8n8.x4.shared.b16 {%0,%1,%2,%3}, [%4];"
                             : "=r"(b[2 * np][0]), "=r"(b[2 * np][1]),
                               "=r"(b[2 * np + 1][0]), "=r"(b[2 * np + 1][1])
                             : "r"(sB + off));
            }
#pragma unroll
            for (int mi = 0; mi < 4; mi++)
#pragma unroll
                for (int ni = 0; ni < 4; ni++) {
                    float* c = acc[mi * 4 + ni];
                    asm volatile(
                        "mma.sync.aligned.m16n8k16.row.col.f32.f16.f16.f32 "
                        "{%0,%1,%2,%3}, {%4,%5,%6,%7}, {%8,%9}, {%0,%1,%2,%3};"
                        : "+f"(c[0]), "+f"(c[1]), "+f"(c[2]), "+f"(c[3])
                        : "r"(a[mi][0]), "r"(a[mi][1]), "r"(a[mi][2]), "r"(a[mi][3]),
                          "r"(b[ni][0]), "r"(b[ni][1]));
                }
        }
        // no bottom barrier (see header comment)
    }

    // epilogue (same fragment->row/col mapping as proven kernels)
    int mb = bm + wm, nb = bn + wn;
#pragma unroll
    for (int mi = 0; mi < 4; mi++)
#pragma unroll
        for (int ni = 0; ni < 4; ni++) {
            float* c = acc[mi * 4 + ni];
            int r0 = mb + mi * 16 + (lane >> 2);
            int c0 = nb + ni * 8 + (lane & 3) * 2;
            float b0 = __ldg(bias + c0), b1 = __ldg(bias + c0 + 1);
            float y0 = c[0] + b0, y1 = c[1] + b1;
            float y2 = c[2] + b0, y3 = c[3] + b1;
            if (EPI == 1) {
                y0 = tanhf(y0); y1 = tanhf(y1); y2 = tanhf(y2); y3 = tanhf(y3);
            }
            if (EPI == 2) {
                __half2 p0; p0.x = __float2half(y0); p0.y = __float2half(y1);
                __half2 p1; p1.x = __float2half(y2); p1.y = __float2half(y3);
                *(__half2*)(Ch + (size_t)r0 * Ntot + c0)       = p0;
                *(__half2*)(Ch + (size_t)(r0 + 8) * Ntot + c0) = p1;
            } else {
                *(float2*)(Cf + (size_t)r0 * Ntot + c0)       = make_float2(y0, y1);
                *(float2*)(Cf + (size_t)(r0 + 8) * Ntot + c0) = make_float2(y2, y3);
            }
        }
}

// ---------------------------------------------------------------------------
// Weight convert: fp32 -> fp16 (8 elems/thread, 16B store)
// ---------------------------------------------------------------------------
__global__ void conv_fp16(const float* __restrict__ in, __half* __restrict__ out, int n8) {
    int i = blockIdx.x * blockDim.x + threadIdx.x;
    if (i >= n8) return;
    float4 v0 = *(const float4*)(in + 8 * i);
    float4 v1 = *(const float4*)(in + 8 * i + 4);
    __half2 h[4];
    h[0].x = __float2half(v0.x); h[0].y = __float2half(v0.y);
    h[1].x = __float2half(v0.z); h[1].y = __float2half(v0.w);
    h[2].x = __float2half(v1.x); h[2].y = __float2half(v1.y);
    h[3].x = __float2half(v1.z); h[3].y = __float2half(v1.w);
    *(uint4*)(out + 8 * i) = *(uint4*)h;
}

// ---------------------------------------------------------------------------
// Moments for the F=2 closed-form LN
// ---------------------------------------------------------------------------
__global__ void moments_kernel(const float* __restrict__ W,
                               const float* __restrict__ bv, int N, int which) {
    int tid = threadIdx.x;
    double acc[9];
#pragma unroll
    for (int q = 0; q < 9; q++) acc[q] = 0.0;
    for (int j = tid; j < N; j += 256) {
        double w0 = W[2 * j], w1 = W[2 * j + 1], b = bv[j];
        acc[0] += w0;      acc[1] += w1;      acc[2] += b;
        acc[3] += w0 * w0; acc[4] += w1 * w1; acc[5] += b * b;
        acc[6] += w0 * w1; acc[7] += w0 * b;  acc[8] += w1 * b;
    }
    __shared__ double sd[256];
    for (int q = 0; q < 9; q++) {
        sd[tid] = acc[q];
        __syncthreads();
        for (int s = 128; s > 0; s >>= 1) {
            if (tid < s) sd[tid] += sd[tid + s];
            __syncthreads();
        }
        if (tid == 0) g_stats[which][q] = (float)(sd[0] / N);
        __syncthreads();
    }
}

// ---------------------------------------------------------------------------
// Layer-1 (elementwise, closed-form LN) -> fp16. act: 0=gelu, 1=silu
// ---------------------------------------------------------------------------
__global__ void layer1_kernel(const float* __restrict__ x, const float* __restrict__ W,
                              const float* __restrict__ bv, const float* __restrict__ gam,
                              const float* __restrict__ bet,
                              __half* __restrict__ oh,
                              int N, int which, int act) {
    int nv = N >> 2;
    int i = blockIdx.x * blockDim.x + threadIdx.x;
    if (i >= BATCH * nv) return;
    int b = i / nv;
    int j = (i - b * nv) << 2;

    float x0 = __ldg(x + 2 * b), x1 = __ldg(x + 2 * b + 1);
    const float* s = g_stats[which];
    float m  = x0 * s[0] + x1 * s[1] + s[2];
    float E2 = x0 * x0 * s[3] + x1 * x1 * s[4] + s[5]
             + 2.f * (x0 * x1 * s[6] + x0 * s[7] + x1 * s[8]);
    float rstd = rsqrtf(fmaxf(E2 - m * m, 0.f) + 1e-5f);

    float4 wA = *(const float4*)(W + 2 * j);
    float4 wB = *(const float4*)(W + 2 * j + 4);
    float4 bb = *(const float4*)(bv + j);
    float4 gg = *(const float4*)(gam + j);
    float4 ee = *(const float4*)(bet + j);

    float y[4];
    y[0] = x0 * wA.x + x1 * wA.y + bb.x;
    y[1] = x0 * wA.z + x1 * wA.w + bb.y;
    y[2] = x0 * wB.x + x1 * wB.y + bb.z;
    y[3] = x0 * wB.z + x1 * wB.w + bb.w;
    float gv[4] = {gg.x, gg.y, gg.z, gg.w};
    float ev[4] = {ee.x, ee.y, ee.z, ee.w};

    __half2 o01, o23;
    float o[4];
#pragma unroll
    for (int q = 0; q < 4; q++) {
        float t = (y[q] - m) * rstd * gv[q] + ev[q];
        if (act == 0) o[q] = 0.5f * t * (1.0f + erff(t * 0.70710678118654752f));
        else          o[q] = t / (1.0f + expf(-t));
    }
    o01.x = __float2half(o[0]); o01.y = __float2half(o[1]);
    o23.x = __float2half(o[2]); o23.y = __float2half(o[3]);
    size_t base = (size_t)b * N + j;
    *(__half2*)(oh + base)     = o01;
    *(__half2*)(oh + base + 2) = o23;
}

// ---------------------------------------------------------------------------
// Row LayerNorm + tanh over N=2048, fp32 in -> fp16 out
// ---------------------------------------------------------------------------
__global__ void ln_tanh_rows(const float* __restrict__ data,
                             const float* __restrict__ gam, const float* __restrict__ bet,
                             __half* __restrict__ oh) {
    const int N = 2048;
    int row = blockIdx.x, tid = threadIdx.x;
    const float* p = data + (size_t)row * N;

    float v[8], s = 0.f, s2 = 0.f;
#pragma unroll
    for (int i = 0; i < 8; i++) {
        float t = p[tid + i * 256];
        v[i] = t; s += t; s2 += t * t;
    }
#pragma unroll
    for (int o = 16; o > 0; o >>= 1) {
        s  += __shfl_down_sync(0xffffffffu, s, o);
        s2 += __shfl_down_sync(0xffffffffu, s2, o);
    }
    __shared__ float sh[2][8];
    __shared__ float mb[2];
    int w = tid >> 5, l = tid & 31;
    if (l == 0) { sh[0][w] = s; sh[1][w] = s2; }
    __syncthreads();
    if (tid == 0) {
        float S = 0.f, S2 = 0.f;
#pragma unroll
        for (int q = 0; q < 8; q++) { S += sh[0][q]; S2 += sh[1][q]; }
        float mean = S / N;
        mb[0] = mean;
        mb[1] = rsqrtf(fmaxf(S2 / N - mean * mean, 0.f) + 1e-5f);
    }
    __syncthreads();
    float mean = mb[0], rstd = mb[1];
    size_t base = (size_t)row * N;
#pragma unroll
    for (int i = 0; i < 8; i++) {
        int c = tid + i * 256;
        float t = tanhf((v[i] - mean) * rstd * gam[c] + bet[c]);
        oh[base + c] = __float2half(t);
    }
}

// ---------------------------------------------------------------------------
// qs mix, fp32 amp/phase in -> fp16 out
// ---------------------------------------------------------------------------
__global__ void qs_kernel(const float* __restrict__ amp, const float* __restrict__ phase,
                          const float* __restrict__ rot_freq, const float* __restrict__ rot_phase,
                          __half* __restrict__ qh) {
    int i = blockIdx.x * blockDim.x + threadIdx.x;
    if (i >= BATCH * (QDIM / 4)) return;
    int j = (i & (QDIM / 4 - 1)) << 2;
    float4 a  = *(const float4*)(amp + (size_t)i * 4);
    float4 ph = *(const float4*)(phase + (size_t)i * 4);
    const float* rf = rot_freq  + (size_t)(4 * QDIM + j) * 3;
    const float* rp = rot_phase + (size_t)(4 * QDIM + j) * 3;
    float av[4] = {a.x, a.y, a.z, a.w};
    float pv[4] = {ph.x, ph.y, ph.z, ph.w};
    float o[4];
#pragma unroll
    for (int q = 0; q < 4; q++) {
        float rx = sinf(av[q] * rf[3 * q + 0] + rp[3 * q + 0]);
        float ry = cosf(pv[q] * rf[3 * q + 1] + rp[3 * q + 1]);
        float rz = tanhf(rp[3 * q + 2]);
        o[q] = (rx + ry + rz) * (1.0f / 3.0f);
    }
    __half2 o01, o23;
    o01.x = __float2half(o[0]); o01.y = __float2half(o[1]);
    o23.x = __float2half(o[2]); o23.y = __float2half(o[3]);
    *(__half2*)(qh + (size_t)i * 4)     = o01;
    *(__half2*)(qh + (size_t)i * 4 + 2) = o23;
}

// ---------------------------------------------------------------------------
// Launch
// ---------------------------------------------------------------------------
static void gemm_run(int epi, const __half* A, const __half* B,
                     const float* bias, float* Cf, __half* Ch, int Ntot, int K) {
    dim3 g(Ntot / BN, BATCH / BM);
    switch (epi) {
    case 0:  gemm_fp16<0><<<g, 256, SMEM_F>>>(A, B, bias, Cf, Ch, Ntot, K); break;
    case 1:  gemm_fp16<1><<<g, 256, SMEM_F>>>(A, B, bias, Cf, Ch, Ntot, K); break;
    default: gemm_fp16<2><<<g, 256, SMEM_F>>>(A, B, bias, Cf, Ch, Ntot, K); break;
    }
}

extern "C" void kernel_launch(void* const* d_in, const int* in_sizes, int n_in,
                              void* d_out, int out_size) {
    const float* x         = (const float*)d_in[0];
    const float* amp_W1    = (const float*)d_in[1];
    const float* amp_b1    = (const float*)d_in[2];
    const float* amp_g1    = (const float*)d_in[3];
    const float* amp_be1   = (const float*)d_in[4];
    const float* amp_W2    = (const float*)d_in[5];
    const float* amp_b2    = (const float*)d_in[6];
    const float* amp_g2    = (const float*)d_in[7];
    const float* amp_be2   = (const float*)d_in[8];
    const float* amp_W3    = (const float*)d_in[9];
    const float* amp_b3    = (const float*)d_in[10];
    const float* ph_W1     = (const float*)d_in[11];
    const float* ph_b1     = (const float*)d_in[12];
    const float* ph_g1     = (const float*)d_in[13];
    const float* ph_be1    = (const float*)d_in[14];
    const float* ph_W2     = (const float*)d_in[15];
    const float* ph_b2     = (const float*)d_in[16];
    const float* rot_freq  = (const float*)d_in[17];
    const float* rot_phase = (const float*)d_in[18];
    const float* attn_in_w = (const float*)d_in[19];
    const float* attn_in_b = (const float*)d_in[20];
    const float* attn_out_w= (const float*)d_in[21];
    const float* attn_out_b= (const float*)d_in[22];
    float* out = (float*)d_out;

    cudaFuncSetAttribute(gemm_fp16<0>, cudaFuncAttributeMaxDynamicSharedMemorySize, SMEM_F);
    cudaFuncSetAttribute(gemm_fp16<1>, cudaFuncAttributeMaxDynamicSharedMemorySize, SMEM_F);
    cudaFuncSetAttribute(gemm_fp16<2>, cudaFuncAttributeMaxDynamicSharedMemorySize, SMEM_F);

#define SYM(p, s) do { void* _t; cudaGetSymbolAddress(&_t, s); p = (decltype(p))_t; } while (0)
    __half *h1, *h2t, *pp, *qs, *v, *w2, *w3, *pw2, *wv, *wo;
    float *h2, *amp, *phs;
    SYM(h1, g_h1);   SYM(h2, g_h2);   SYM(h2t, g_h2t);
    SYM(pp, g_p);    SYM(amp, g_amp); SYM(phs, g_phs);
    SYM(qs, g_qs);   SYM(v, g_v);
    SYM(w2, g_w2);   SYM(w3, g_w3);   SYM(pw2, g_pw2);
    SYM(wv, g_wv);   SYM(wo, g_wo);
#undef SYM

    moments_kernel<<<1, 256>>>(amp_W1, amp_b1, N1, 0);
    moments_kernel<<<1, 256>>>(ph_W1,  ph_b1,  N2, 1);

    {
        int n8;
        n8 = N2 * N1 / 8;     conv_fp16<<<(n8 + 255) / 256, 256>>>(amp_W2, w2, n8);
        n8 = QDIM * N2 / 8;   conv_fp16<<<(n8 + 255) / 256, 256>>>(amp_W3, w3, n8);
        n8 = QDIM * N2 / 8;   conv_fp16<<<(n8 + 255) / 256, 256>>>(ph_W2, pw2, n8);
        n8 = QDIM * QDIM / 8; conv_fp16<<<(n8 + 255) / 256, 256>>>(
            attn_in_w + (size_t)2 * QDIM * QDIM, wv, n8);
        n8 = QDIM * QDIM / 8; conv_fp16<<<(n8 + 255) / 256, 256>>>(attn_out_w, wo, n8);
    }

    layer1_kernel<<<(BATCH * (N1 / 4) + 255) / 256, 256>>>(
        x, amp_W1, amp_b1, amp_g1, amp_be1, h1, N1, 0, 0);
    layer1_kernel<<<(BATCH * (N2 / 4) + 255) / 256, 256>>>(
        x, ph_W1, ph_b1, ph_g1, ph_be1, pp, N2, 1, 1);

    // GEMM1: h2 = h1 @ W2^T + b2 (fp32 out)
    gemm_run(0, h1, w2, amp_b2, h2, nullptr, N2, N1);
    ln_tanh_rows<<<BATCH, 256>>>(h2, amp_g2, amp_be2, h2t);
    // GEMM2: amp = h2t @ W3^T + b3
    gemm_run(0, h2t, w3, amp_b3, amp, nullptr, QDIM, N2);
    // GEMM3: phase = tanh(p @ phW2^T + b2)
    gemm_run(1, pp, pw2, ph_b2, phs, nullptr, QDIM, N2);
    // qs mix
    qs_kernel<<<(BATCH * (QDIM / 4) + 255) / 256, 256>>>(amp, phs, rot_freq, rot_phase, qs);
    // GEMM4: v = qs @ Wv^T + bv (fp16 out)
    gemm_run(2, qs, wv, attn_in_b + 2 * QDIM, nullptr, v, QDIM, QDIM);
    // GEMM5: out = v @ Wout^T + bout
    gemm_run(0, v, wo, attn_out_b, out, nullptr, QDIM, QDIM);
}